// round 1
// baseline (speedup 1.0000x reference)
#include <cuda_runtime.h>
#include <math.h>

#define BB 8
#define TT 1024
#define EE 1024
#define HH 16
#define SS 64

// Scratch (device globals — no allocation allowed)
__device__ float g_q[BB*HH*TT*SS];   // [b][h][t][s], pre-scaled by E^-0.25
__device__ float g_k[BB*HH*TT*SS];   // [b][h][t][s], pre-scaled by E^-0.25
__device__ float g_v[BB*HH*TT*SS];   // [b][h][t][s]
__device__ float g_ao[BB*TT*EE];     // attention output, [b][t][h*64+s]

// ---------------------------------------------------------------------------
// Kernel 1: QKV projections.
// Block: 256 threads, 16 tokens. Smem: 3 transposed 64x64 weights + x tile.
// Each thread task: 4 outputs (one head, one matrix) x 4 tokens microtile.
// ---------------------------------------------------------------------------
#define QKV_TOK 16
#define QKV_SMEM_BYTES ((3*4096 + QKV_TOK*EE) * 4)

__global__ __launch_bounds__(256) void qkv_kernel(
    const float* __restrict__ x,
    const float* __restrict__ Wq,
    const float* __restrict__ Wk,
    const float* __restrict__ Wv)
{
    extern __shared__ float sm[];
    float* Wt = sm;              // Wt[w][s*64+o] = W[o*64+s]
    float* xs = sm + 3*4096;     // xs[tok][1024]

    const int tid = threadIdx.x;

    // Load weights transposed
    for (int idx = tid; idx < 3*4096; idx += 256) {
        int w = idx >> 12, r = idx & 4095;
        int o = r >> 6,    s = r & 63;
        const float* W = (w == 0) ? Wq : (w == 1) ? Wk : Wv;
        Wt[(w << 12) + (s << 6) + o] = W[r];
    }
    // Load x tile (coalesced float4)
    const int bt0 = blockIdx.x * QKV_TOK;
    const float4* xg = (const float4*)(x + (size_t)bt0 * EE);
    float4* xs4 = (float4*)xs;
    for (int idx = tid; idx < QKV_TOK*EE/4; idx += 256)
        xs4[idx] = xg[idx];
    __syncthreads();

    const float qkscale = 0.17677669529663687f;  // 1024^-0.25

    // 3072 outputs/token * 16 tokens -> 3072 tasks of (4 outs x 4 toks)
    #pragma unroll 1
    for (int iter = 0; iter < 12; iter++) {
        int task  = iter*256 + tid;
        int chunk = task / 768;          // which 4-token group
        int quad  = task - chunk*768;    // which 4-output column quad
        int col   = quad << 2;
        int w     = col >> 10;           // 0=q, 1=k, 2=v
        int rem   = col & 1023;
        int h     = rem >> 6;
        int o     = rem & 63;

        float acc[4][4];
        #pragma unroll
        for (int a = 0; a < 4; a++)
            #pragma unroll
            for (int c = 0; c < 4; c++) acc[a][c] = 0.f;

        const float* wrow = Wt + (w << 12) + o;
        const float* xrow = xs + (size_t)(chunk*4)*EE + (h << 6);
        #pragma unroll
        for (int s = 0; s < 64; s++) {
            float4 wv = *(const float4*)(wrow + (s << 6));
            #pragma unroll
            for (int tk = 0; tk < 4; tk++) {
                float xv = xrow[(size_t)tk*EE + s];
                acc[tk][0] += xv * wv.x;
                acc[tk][1] += xv * wv.y;
                acc[tk][2] += xv * wv.z;
                acc[tk][3] += xv * wv.w;
            }
        }

        float scale = (w == 2) ? 1.f : qkscale;
        float* dst  = (w == 0) ? g_q : (w == 1) ? g_k : g_v;
        #pragma unroll
        for (int tk = 0; tk < 4; tk++) {
            int bt = bt0 + chunk*4 + tk;
            int b  = bt >> 10, t = bt & 1023;
            float4 v;
            v.x = acc[tk][0]*scale; v.y = acc[tk][1]*scale;
            v.z = acc[tk][2]*scale; v.w = acc[tk][3]*scale;
            *(float4*)(dst + ((((size_t)b*HH + h)*TT + t) << 6) + o) = v;
        }
    }
}

// ---------------------------------------------------------------------------
// Kernel 2: flash attention (fp32), causal + length mask.
// Block = one (b,h) x 64-query tile. 256 threads, 4x4 microtiles.
// Smem: Qt/Kt transposed [s][row] pad 68, Vs [key][s] pad 68, Pt [key][row].
// ---------------------------------------------------------------------------
#define PADW 68
#define ATTN_SMEM_BYTES (4*64*PADW*4)

__global__ __launch_bounds__(256) void attn_kernel(const int* __restrict__ lengths)
{
    extern __shared__ float sm[];
    float* Qt = sm;
    float* Kt = Qt + 64*PADW;
    float* Vs = Kt + 64*PADW;
    float* Pt = Vs + 64*PADW;

    const int qt = blockIdx.x;        // query tile index (0..15)
    const int bh = blockIdx.y;        // b*H + h
    const int b  = bh >> 4;
    const int h  = bh & 15;
    const int q0 = qt << 6;
    const int len = lengths[b];

    const int tid  = threadIdx.x;
    const int tx   = tid & 15;        // score-column group
    const int ty   = tid >> 4;        // score-row group
    const int sidx = tid & 15;        // load lane
    const int rbase = tid >> 4;

    const float* qg = g_q + (size_t)bh*TT*SS;
    const float* kg = g_k + (size_t)bh*TT*SS;
    const float* vg = g_v + (size_t)bh*TT*SS;

    // Load Q tile transposed: Qt[s][r]
    #pragma unroll
    for (int pass = 0; pass < 4; pass++) {
        int r = rbase + pass*16;
        float4 v = *(const float4*)(qg + (size_t)(q0 + r)*64 + sidx*4);
        Qt[(sidx*4+0)*PADW + r] = v.x;
        Qt[(sidx*4+1)*PADW + r] = v.y;
        Qt[(sidx*4+2)*PADW + r] = v.z;
        Qt[(sidx*4+3)*PADW + r] = v.w;
    }

    float m[4], l[4], o[4][4];
    #pragma unroll
    for (int i = 0; i < 4; i++) {
        m[i] = -INFINITY; l[i] = 0.f;
        #pragma unroll
        for (int j = 0; j < 4; j++) o[i][j] = 0.f;
    }

    for (int kt = 0; kt <= qt; kt++) {
        int k0 = kt << 6;
        if (k0 >= len) break;
        __syncthreads();
        // Load K transposed + V row-major
        #pragma unroll
        for (int pass = 0; pass < 4; pass++) {
            int r = rbase + pass*16;
            float4 v = *(const float4*)(kg + (size_t)(k0 + r)*64 + sidx*4);
            Kt[(sidx*4+0)*PADW + r] = v.x;
            Kt[(sidx*4+1)*PADW + r] = v.y;
            Kt[(sidx*4+2)*PADW + r] = v.z;
            Kt[(sidx*4+3)*PADW + r] = v.w;
            float4 vv = *(const float4*)(vg + (size_t)(k0 + r)*64 + sidx*4);
            *(float4*)(Vs + r*PADW + sidx*4) = vv;
        }
        __syncthreads();

        // S = Q K^T  (4x4 per thread)
        float sc[4][4];
        #pragma unroll
        for (int i = 0; i < 4; i++)
            #pragma unroll
            for (int j = 0; j < 4; j++) sc[i][j] = 0.f;
        #pragma unroll
        for (int kk = 0; kk < 64; kk++) {
            float4 a  = *(const float4*)(Qt + kk*PADW + ty*4);
            float4 bb = *(const float4*)(Kt + kk*PADW + tx*4);
            float ar[4] = {a.x, a.y, a.z, a.w};
            float br[4] = {bb.x, bb.y, bb.z, bb.w};
            #pragma unroll
            for (int i = 0; i < 4; i++)
                #pragma unroll
                for (int j = 0; j < 4; j++)
                    sc[i][j] += ar[i] * br[j];
        }

        // Mask (causal on diagonal tile; length mask if tile crosses len)
        bool needmask = (kt == qt) || (k0 + 64 > len);
        if (needmask) {
            #pragma unroll
            for (int i = 0; i < 4; i++) {
                int qgi = q0 + ty*4 + i;
                #pragma unroll
                for (int j = 0; j < 4; j++) {
                    int kgi = k0 + tx*4 + j;
                    if (kgi > qgi || kgi >= len) sc[i][j] = -INFINITY;
                }
            }
        }

        // Online softmax per row (16-lane group reduction)
        #pragma unroll
        for (int i = 0; i < 4; i++) {
            float rm = fmaxf(fmaxf(sc[i][0], sc[i][1]), fmaxf(sc[i][2], sc[i][3]));
            rm = fmaxf(rm, __shfl_xor_sync(0xffffffffu, rm, 1));
            rm = fmaxf(rm, __shfl_xor_sync(0xffffffffu, rm, 2));
            rm = fmaxf(rm, __shfl_xor_sync(0xffffffffu, rm, 4));
            rm = fmaxf(rm, __shfl_xor_sync(0xffffffffu, rm, 8));
            float mn   = fmaxf(m[i], rm);
            float corr = __expf(m[i] - mn);
            float rs = 0.f;
            #pragma unroll
            for (int j = 0; j < 4; j++) {
                sc[i][j] = __expf(sc[i][j] - mn);
                rs += sc[i][j];
            }
            rs += __shfl_xor_sync(0xffffffffu, rs, 1);
            rs += __shfl_xor_sync(0xffffffffu, rs, 2);
            rs += __shfl_xor_sync(0xffffffffu, rs, 4);
            rs += __shfl_xor_sync(0xffffffffu, rs, 8);
            l[i] = l[i]*corr + rs;
            m[i] = mn;
            #pragma unroll
            for (int j = 0; j < 4; j++) o[i][j] *= corr;
        }

        // Stage P transposed: Pt[key][qrow]
        #pragma unroll
        for (int j = 0; j < 4; j++) {
            float4 pv = make_float4(sc[0][j], sc[1][j], sc[2][j], sc[3][j]);
            *(float4*)(Pt + (tx*4 + j)*PADW + ty*4) = pv;
        }
        __syncthreads();

        // O += P V  (4x4 per thread)
        #pragma unroll
        for (int kk = 0; kk < 64; kk++) {
            float4 a  = *(const float4*)(Pt + kk*PADW + ty*4);
            float4 bb = *(const float4*)(Vs + kk*PADW + tx*4);
            float ar[4] = {a.x, a.y, a.z, a.w};
            float br[4] = {bb.x, bb.y, bb.z, bb.w};
            #pragma unroll
            for (int i = 0; i < 4; i++)
                #pragma unroll
                for (int j = 0; j < 4; j++)
                    o[i][j] += ar[i] * br[j];
        }
    }

    // Normalize and write to g_ao[b][t][h*64+c]
    #pragma unroll
    for (int i = 0; i < 4; i++) {
        float inv = 1.f / l[i];
        int t = q0 + ty*4 + i;
        float4 v = make_float4(o[i][0]*inv, o[i][1]*inv, o[i][2]*inv, o[i][3]*inv);
        *(float4*)(g_ao + ((size_t)b*TT + t)*EE + (h << 6) + tx*4) = v;
    }
}

// ---------------------------------------------------------------------------
// Kernel 3: output projection out = g_ao @ Wu^T + bu.
// Classic SGEMM: 128x128 block tile, K=8, 256 threads, 8x8 microtiles.
// ---------------------------------------------------------------------------
__global__ __launch_bounds__(256) void out_gemm(
    const float* __restrict__ Wu,
    const float* __restrict__ bu,
    float* __restrict__ out)
{
    __shared__ float As[8][132];
    __shared__ float Bs[8][132];

    const int tid = threadIdx.x;
    const int tx = tid & 15, ty = tid >> 4;
    const int m0 = blockIdx.y << 7, n0 = blockIdx.x << 7;
    const int lm = tid >> 1, lp = tid & 1;
    const float* A = g_ao;

    float acc[8][8];
    #pragma unroll
    for (int i = 0; i < 8; i++)
        #pragma unroll
        for (int j = 0; j < 8; j++) acc[i][j] = 0.f;

    for (int e0 = 0; e0 < 1024; e0 += 8) {
        float4 av = *(const float4*)(A  + (size_t)(m0 + lm)*1024 + e0 + lp*4);
        float4 bv = *(const float4*)(Wu + (size_t)(n0 + lm)*1024 + e0 + lp*4);
        __syncthreads();
        As[lp*4+0][lm] = av.x; As[lp*4+1][lm] = av.y;
        As[lp*4+2][lm] = av.z; As[lp*4+3][lm] = av.w;
        Bs[lp*4+0][lm] = bv.x; Bs[lp*4+1][lm] = bv.y;
        Bs[lp*4+2][lm] = bv.z; Bs[lp*4+3][lm] = bv.w;
        __syncthreads();
        #pragma unroll
        for (int kk = 0; kk < 8; kk++) {
            float a[8], bb[8];
            *(float4*)(a)    = *(const float4*)&As[kk][ty*8];
            *(float4*)(a+4)  = *(const float4*)&As[kk][ty*8+4];
            *(float4*)(bb)   = *(const float4*)&Bs[kk][tx*8];
            *(float4*)(bb+4) = *(const float4*)&Bs[kk][tx*8+4];
            #pragma unroll
            for (int i = 0; i < 8; i++)
                #pragma unroll
                for (int j = 0; j < 8; j++)
                    acc[i][j] += a[i] * bb[j];
        }
    }

    float bias[8];
    *(float4*)(bias)   = *(const float4*)(bu + n0 + tx*8);
    *(float4*)(bias+4) = *(const float4*)(bu + n0 + tx*8 + 4);

    #pragma unroll
    for (int i = 0; i < 8; i++) {
        size_t row = (size_t)(m0 + ty*8 + i);
        float4 v0 = make_float4(acc[i][0]+bias[0], acc[i][1]+bias[1],
                                acc[i][2]+bias[2], acc[i][3]+bias[3]);
        float4 v1 = make_float4(acc[i][4]+bias[4], acc[i][5]+bias[5],
                                acc[i][6]+bias[6], acc[i][7]+bias[7]);
        *(float4*)(out + row*1024 + n0 + tx*8)     = v0;
        *(float4*)(out + row*1024 + n0 + tx*8 + 4) = v1;
    }
}

// ---------------------------------------------------------------------------
extern "C" void kernel_launch(void* const* d_in, const int* in_sizes, int n_in,
                              void* d_out, int out_size)
{
    (void)in_sizes; (void)n_in; (void)out_size;
    const float* x       = (const float*)d_in[0];
    const int*   lengths = (const int*)  d_in[1];
    const float* Wk      = (const float*)d_in[2];
    const float* Wq      = (const float*)d_in[3];
    const float* Wv      = (const float*)d_in[4];
    const float* Wu      = (const float*)d_in[5];
    const float* bu      = (const float*)d_in[6];
    float* out = (float*)d_out;

    cudaFuncSetAttribute(qkv_kernel,  cudaFuncAttributeMaxDynamicSharedMemorySize,
                         QKV_SMEM_BYTES);
    cudaFuncSetAttribute(attn_kernel, cudaFuncAttributeMaxDynamicSharedMemorySize,
                         ATTN_SMEM_BYTES);

    qkv_kernel<<<(BB*TT)/QKV_TOK, 256, QKV_SMEM_BYTES>>>(x, Wq, Wk, Wv);
    attn_kernel<<<dim3(TT/64, BB*HH), 256, ATTN_SMEM_BYTES>>>(lengths);
    out_gemm<<<dim3(EE/128, (BB*TT)/128), 256>>>(Wu, bu, out);
}

// round 3
// speedup vs baseline: 1.2330x; 1.2330x over previous
#include <cuda_runtime.h>
#include <cuda_bf16.h>
#include <math.h>
#include <stdint.h>

#define BB 8
#define TT 1024
#define EE 1024
#define HH 16
#define SS 64

// Scratch (device globals — no allocation allowed)
__device__ float g_q[BB*HH*TT*SS];   // [b][h][t][s], pre-scaled by E^-0.25
__device__ float g_k[BB*HH*TT*SS];
__device__ float g_v[BB*HH*TT*SS];
__device__ float g_ao[BB*TT*EE];     // attention output, [bt][e]
__device__ __nv_bfloat16 g_Ah[BB*TT*EE];
__device__ __nv_bfloat16 g_Al[BB*TT*EE];
__device__ __nv_bfloat16 g_Wh[EE*EE];
__device__ __nv_bfloat16 g_Wl[EE*EE];

// ---------------------------------------------------------------------------
// Helpers
// ---------------------------------------------------------------------------
__device__ __forceinline__ uint32_t smem_u32(const void* p) {
    uint32_t a;
    asm("{ .reg .u64 t; cvta.to.shared.u64 t, %1; cvt.u32.u64 %0, t; }"
        : "=r"(a) : "l"(p));
    return a;
}

#define CP16(dst, src) \
    asm volatile("cp.async.cg.shared.global [%0], [%1], 16;" :: "r"(dst), "l"(src) : "memory")

#define LDSM4(r, addr) \
    asm volatile("ldmatrix.sync.aligned.m8n8.x4.shared.b16 {%0,%1,%2,%3}, [%4];" \
        : "=r"((r)[0]), "=r"((r)[1]), "=r"((r)[2]), "=r"((r)[3]) : "r"(addr))

#define MMA16816(c, a, b0, b1) \
    asm volatile("mma.sync.aligned.m16n8k16.row.col.f32.bf16.bf16.f32 " \
        "{%0,%1,%2,%3}, {%4,%5,%6,%7}, {%8,%9}, {%0,%1,%2,%3};" \
        : "+f"((c)[0]), "+f"((c)[1]), "+f"((c)[2]), "+f"((c)[3]) \
        : "r"((a)[0]), "r"((a)[1]), "r"((a)[2]), "r"((a)[3]), "r"(b0), "r"(b1))

// ---------------------------------------------------------------------------
// Kernel 1: QKV projections (fp32, unchanged).
// ---------------------------------------------------------------------------
#define QKV_TOK 16
#define QKV_SMEM_BYTES ((3*4096 + QKV_TOK*EE) * 4)

__global__ __launch_bounds__(256) void qkv_kernel(
    const float* __restrict__ x,
    const float* __restrict__ Wq,
    const float* __restrict__ Wk,
    const float* __restrict__ Wv)
{
    extern __shared__ float sm[];
    float* Wt = sm;
    float* xs = sm + 3*4096;

    const int tid = threadIdx.x;

    for (int idx = tid; idx < 3*4096; idx += 256) {
        int w = idx >> 12, r = idx & 4095;
        int o = r >> 6,    s = r & 63;
        const float* W = (w == 0) ? Wq : (w == 1) ? Wk : Wv;
        Wt[(w << 12) + (s << 6) + o] = W[r];
    }
    const int bt0 = blockIdx.x * QKV_TOK;
    const float4* xg = (const float4*)(x + (size_t)bt0 * EE);
    float4* xs4 = (float4*)xs;
    for (int idx = tid; idx < QKV_TOK*EE/4; idx += 256)
        xs4[idx] = xg[idx];
    __syncthreads();

    const float qkscale = 0.17677669529663687f;  // 1024^-0.25

    #pragma unroll 1
    for (int iter = 0; iter < 12; iter++) {
        int task  = iter*256 + tid;
        int chunk = task / 768;
        int quad  = task - chunk*768;
        int col   = quad << 2;
        int w     = col >> 10;
        int rem   = col & 1023;
        int h     = rem >> 6;
        int o     = rem & 63;

        float acc[4][4];
        #pragma unroll
        for (int a = 0; a < 4; a++)
            #pragma unroll
            for (int c = 0; c < 4; c++) acc[a][c] = 0.f;

        const float* wrow = Wt + (w << 12) + o;
        const float* xrow = xs + (size_t)(chunk*4)*EE + (h << 6);
        #pragma unroll
        for (int s = 0; s < 64; s++) {
            float4 wv = *(const float4*)(wrow + (s << 6));
            #pragma unroll
            for (int tk = 0; tk < 4; tk++) {
                float xv = xrow[(size_t)tk*EE + s];
                acc[tk][0] += xv * wv.x;
                acc[tk][1] += xv * wv.y;
                acc[tk][2] += xv * wv.z;
                acc[tk][3] += xv * wv.w;
            }
        }

        float scale = (w == 2) ? 1.f : qkscale;
        float* dst  = (w == 0) ? g_q : (w == 1) ? g_k : g_v;
        #pragma unroll
        for (int tk = 0; tk < 4; tk++) {
            int bt = bt0 + chunk*4 + tk;
            int b  = bt >> 10, t = bt & 1023;
            float4 v;
            v.x = acc[tk][0]*scale; v.y = acc[tk][1]*scale;
            v.z = acc[tk][2]*scale; v.w = acc[tk][3]*scale;
            *(float4*)(dst + ((((size_t)b*HH + h)*TT + t) << 6) + o) = v;
        }
    }
}

// ---------------------------------------------------------------------------
// Kernel 2: flash attention (fp32, unchanged).
// ---------------------------------------------------------------------------
#define PADW 68
#define ATTN_SMEM_BYTES (4*64*PADW*4)

__global__ __launch_bounds__(256) void attn_kernel(const int* __restrict__ lengths)
{
    extern __shared__ float sm[];
    float* Qt = sm;
    float* Kt = Qt + 64*PADW;
    float* Vs = Kt + 64*PADW;
    float* Pt = Vs + 64*PADW;

    const int qt = blockIdx.x;
    const int bh = blockIdx.y;
    const int b  = bh >> 4;
    const int h  = bh & 15;
    const int q0 = qt << 6;
    const int len = lengths[b];

    const int tid  = threadIdx.x;
    const int tx   = tid & 15;
    const int ty   = tid >> 4;
    const int sidx = tid & 15;
    const int rbase = tid >> 4;

    const float* qg = g_q + (size_t)bh*TT*SS;
    const float* kg = g_k + (size_t)bh*TT*SS;
    const float* vg = g_v + (size_t)bh*TT*SS;

    #pragma unroll
    for (int pass = 0; pass < 4; pass++) {
        int r = rbase + pass*16;
        float4 v = *(const float4*)(qg + (size_t)(q0 + r)*64 + sidx*4);
        Qt[(sidx*4+0)*PADW + r] = v.x;
        Qt[(sidx*4+1)*PADW + r] = v.y;
        Qt[(sidx*4+2)*PADW + r] = v.z;
        Qt[(sidx*4+3)*PADW + r] = v.w;
    }

    float m[4], l[4], o[4][4];
    #pragma unroll
    for (int i = 0; i < 4; i++) {
        m[i] = -INFINITY; l[i] = 0.f;
        #pragma unroll
        for (int j = 0; j < 4; j++) o[i][j] = 0.f;
    }

    for (int kt = 0; kt <= qt; kt++) {
        int k0 = kt << 6;
        if (k0 >= len) break;
        __syncthreads();
        #pragma unroll
        for (int pass = 0; pass < 4; pass++) {
            int r = rbase + pass*16;
            float4 v = *(const float4*)(kg + (size_t)(k0 + r)*64 + sidx*4);
            Kt[(sidx*4+0)*PADW + r] = v.x;
            Kt[(sidx*4+1)*PADW + r] = v.y;
            Kt[(sidx*4+2)*PADW + r] = v.z;
            Kt[(sidx*4+3)*PADW + r] = v.w;
            float4 vv = *(const float4*)(vg + (size_t)(k0 + r)*64 + sidx*4);
            *(float4*)(Vs + r*PADW + sidx*4) = vv;
        }
        __syncthreads();

        float sc[4][4];
        #pragma unroll
        for (int i = 0; i < 4; i++)
            #pragma unroll
            for (int j = 0; j < 4; j++) sc[i][j] = 0.f;
        #pragma unroll
        for (int kk = 0; kk < 64; kk++) {
            float4 a  = *(const float4*)(Qt + kk*PADW + ty*4);
            float4 bb = *(const float4*)(Kt + kk*PADW + tx*4);
            float ar[4] = {a.x, a.y, a.z, a.w};
            float br[4] = {bb.x, bb.y, bb.z, bb.w};
            #pragma unroll
            for (int i = 0; i < 4; i++)
                #pragma unroll
                for (int j = 0; j < 4; j++)
                    sc[i][j] += ar[i] * br[j];
        }

        bool needmask = (kt == qt) || (k0 + 64 > len);
        if (needmask) {
            #pragma unroll
            for (int i = 0; i < 4; i++) {
                int qgi = q0 + ty*4 + i;
                #pragma unroll
                for (int j = 0; j < 4; j++) {
                    int kgi = k0 + tx*4 + j;
                    if (kgi > qgi || kgi >= len) sc[i][j] = -INFINITY;
                }
            }
        }

        #pragma unroll
        for (int i = 0; i < 4; i++) {
            float rm = fmaxf(fmaxf(sc[i][0], sc[i][1]), fmaxf(sc[i][2], sc[i][3]));
            rm = fmaxf(rm, __shfl_xor_sync(0xffffffffu, rm, 1));
            rm = fmaxf(rm, __shfl_xor_sync(0xffffffffu, rm, 2));
            rm = fmaxf(rm, __shfl_xor_sync(0xffffffffu, rm, 4));
            rm = fmaxf(rm, __shfl_xor_sync(0xffffffffu, rm, 8));
            float mn   = fmaxf(m[i], rm);
            float corr = __expf(m[i] - mn);
            float rs = 0.f;
            #pragma unroll
            for (int j = 0; j < 4; j++) {
                sc[i][j] = __expf(sc[i][j] - mn);
                rs += sc[i][j];
            }
            rs += __shfl_xor_sync(0xffffffffu, rs, 1);
            rs += __shfl_xor_sync(0xffffffffu, rs, 2);
            rs += __shfl_xor_sync(0xffffffffu, rs, 4);
            rs += __shfl_xor_sync(0xffffffffu, rs, 8);
            l[i] = l[i]*corr + rs;
            m[i] = mn;
            #pragma unroll
            for (int j = 0; j < 4; j++) o[i][j] *= corr;
        }

        #pragma unroll
        for (int j = 0; j < 4; j++) {
            float4 pv = make_float4(sc[0][j], sc[1][j], sc[2][j], sc[3][j]);
            *(float4*)(Pt + (tx*4 + j)*PADW + ty*4) = pv;
        }
        __syncthreads();

        #pragma unroll
        for (int kk = 0; kk < 64; kk++) {
            float4 a  = *(const float4*)(Pt + kk*PADW + ty*4);
            float4 bb = *(const float4*)(Vs + kk*PADW + tx*4);
            float ar[4] = {a.x, a.y, a.z, a.w};
            float br[4] = {bb.x, bb.y, bb.z, bb.w};
            #pragma unroll
            for (int i = 0; i < 4; i++)
                #pragma unroll
                for (int j = 0; j < 4; j++)
                    o[i][j] += ar[i] * br[j];
        }
    }

    #pragma unroll
    for (int i = 0; i < 4; i++) {
        float inv = 1.f / l[i];
        int t = q0 + ty*4 + i;
        float4 v = make_float4(o[i][0]*inv, o[i][1]*inv, o[i][2]*inv, o[i][3]*inv);
        *(float4*)(g_ao + ((size_t)b*TT + t)*EE + (h << 6) + tx*4) = v;
    }
}

// ---------------------------------------------------------------------------
// Split fp32 -> (hi, lo) bf16.
// ---------------------------------------------------------------------------
__global__ __launch_bounds__(256) void split_W_kernel(const float* __restrict__ src)
{
    int i = blockIdx.x*256 + threadIdx.x;
    float4 v = ((const float4*)src)[i];
    float f[4] = {v.x, v.y, v.z, v.w};
    __nv_bfloat16 h[4], l[4];
    #pragma unroll
    for (int j = 0; j < 4; j++) {
        h[j] = __float2bfloat16(f[j]);
        l[j] = __float2bfloat16(f[j] - __bfloat162float(h[j]));
    }
    __nv_bfloat162* hp = (__nv_bfloat162*)g_Wh;
    __nv_bfloat162* lp = (__nv_bfloat162*)g_Wl;
    hp[i*2+0] = __nv_bfloat162(h[0], h[1]);
    hp[i*2+1] = __nv_bfloat162(h[2], h[3]);
    lp[i*2+0] = __nv_bfloat162(l[0], l[1]);
    lp[i*2+1] = __nv_bfloat162(l[2], l[3]);
}

__global__ __launch_bounds__(256) void split_A_kernel()
{
    int i = blockIdx.x*256 + threadIdx.x;
    float4 v = ((const float4*)g_ao)[i];
    float f[4] = {v.x, v.y, v.z, v.w};
    __nv_bfloat16 h[4], l[4];
    #pragma unroll
    for (int j = 0; j < 4; j++) {
        h[j] = __float2bfloat16(f[j]);
        l[j] = __float2bfloat16(f[j] - __bfloat162float(h[j]));
    }
    __nv_bfloat162* hp = (__nv_bfloat162*)g_Ah;
    __nv_bfloat162* lp = (__nv_bfloat162*)g_Al;
    hp[i*2+0] = __nv_bfloat162(h[0], h[1]);
    hp[i*2+1] = __nv_bfloat162(h[2], h[3]);
    lp[i*2+0] = __nv_bfloat162(l[0], l[1]);
    lp[i*2+1] = __nv_bfloat162(l[2], l[3]);
}

// ---------------------------------------------------------------------------
// Kernel 3: out = A @ Wu^T + bu via mma.sync bf16 split-precision (3 passes).
// CTA tile 128x128, 8 warps (2m x 4n), warp tile 64x32, K-chunk 64,
// double-buffered cp.async, padded smem rows (72 bf16) for conflict-free
// ldmatrix.
// ---------------------------------------------------------------------------
#define SPAD 72
#define TILE_BYTES (128*SPAD*2)       // 18432
#define GEMM_SMEM (4*TILE_BYTES)      // A0,B0,A1,B1 = 73728

__global__ __launch_bounds__(256) void out_gemm_mma(
    const float* __restrict__ bu,
    float* __restrict__ out)
{
    extern __shared__ __align__(16) char smc[];
    const uint32_t sb = smem_u32(smc);

    const int tid  = threadIdx.x;
    const int warp = tid >> 5;
    const int lane = tid & 31;
    const int m0 = blockIdx.y << 7;
    const int n0 = blockIdx.x << 7;

    const int wm = warp >> 2;          // 0..1  -> m offset wm*64
    const int wn = warp & 3;           // 0..3  -> n offset wn*32

    // ldmatrix per-lane addressing
    const int a_row = (lane & 7) + ((lane >> 3) & 1) * 8;   // row within 16
    const int a_kh  = (lane >> 4) * 8;                      // k half
    const int b_row = (lane & 7) + ((lane >> 4) & 1) * 8;   // n within 16
    const int b_kh  = ((lane >> 3) & 1) * 8;                // k half

    float acc[4][4][4];
    #pragma unroll
    for (int i = 0; i < 4; i++)
        #pragma unroll
        for (int j = 0; j < 4; j++)
            #pragma unroll
            for (int q = 0; q < 4; q++) acc[i][j][q] = 0.f;

    // --- chunk loader: it in [0,48) -> pass = it/16, kc = it%16 ---
    #define LOAD_CHUNK(it_, buf_) do {                                        \
        int pass_ = (it_) >> 4, kc_ = (it_) & 15, k0_ = kc_ << 6;             \
        const __nv_bfloat16* Asrc = (pass_ == 2) ? g_Al : g_Ah;               \
        const __nv_bfloat16* Bsrc = (pass_ == 1) ? g_Wl : g_Wh;               \
        uint32_t dA = sb + (buf_) * (2*TILE_BYTES);                           \
        uint32_t dB = dA + TILE_BYTES;                                        \
        _Pragma("unroll")                                                     \
        for (int i_ = 0; i_ < 4; i_++) {                                      \
            int o_ = tid + (i_ << 8);                                         \
            int row_ = o_ >> 3, seg_ = o_ & 7;                                \
            CP16(dA + row_*144 + seg_*16,                                     \
                 Asrc + (((size_t)(m0 + row_)) << 10) + k0_ + seg_*8);        \
            CP16(dB + row_*144 + seg_*16,                                     \
                 Bsrc + (((size_t)(n0 + row_)) << 10) + k0_ + seg_*8);        \
        }                                                                     \
        asm volatile("cp.async.commit_group;" ::: "memory");                  \
    } while (0)

    LOAD_CHUNK(0, 0);

    #pragma unroll 1
    for (int it = 0; it < 48; it++) {
        const int buf = it & 1;
        if (it + 1 < 48) {
            LOAD_CHUNK(it + 1, buf ^ 1);
            asm volatile("cp.async.wait_group 1;" ::: "memory");
        } else {
            asm volatile("cp.async.wait_group 0;" ::: "memory");
        }
        __syncthreads();

        const uint32_t aBase = sb + buf * (2*TILE_BYTES);
        const uint32_t bBase = aBase + TILE_BYTES;

        #pragma unroll
        for (int ks = 0; ks < 4; ks++) {
            const int k16 = ks << 4;
            uint32_t af[4][4];
            #pragma unroll
            for (int mi = 0; mi < 4; mi++) {
                uint32_t addr = aBase +
                    (uint32_t)(((wm*64 + mi*16 + a_row) * SPAD + k16 + a_kh) * 2);
                LDSM4(af[mi], addr);
            }
            uint32_t bf[2][4];
            #pragma unroll
            for (int bj = 0; bj < 2; bj++) {
                uint32_t addr = bBase +
                    (uint32_t)(((wn*32 + bj*16 + b_row) * SPAD + k16 + b_kh) * 2);
                LDSM4(bf[bj], addr);
            }
            #pragma unroll
            for (int mi = 0; mi < 4; mi++)
                #pragma unroll
                for (int nj = 0; nj < 4; nj++) {
                    uint32_t b0 = bf[nj >> 1][(nj & 1) * 2];
                    uint32_t b1 = bf[nj >> 1][(nj & 1) * 2 + 1];
                    MMA16816(acc[mi][nj], af[mi], b0, b1);
                }
        }
        __syncthreads();
    }

    // Epilogue: add bias, write fp32.
    const int r0 = lane >> 2;
    const int cp = (lane & 3) * 2;
    #pragma unroll
    for (int mi = 0; mi < 4; mi++) {
        #pragma unroll
        for (int nj = 0; nj < 4; nj++) {
            int gm = m0 + wm*64 + mi*16 + r0;
            int gn = n0 + wn*32 + nj*8 + cp;
            float b0 = bu[gn], b1 = bu[gn + 1];
            float2 v0 = make_float2(acc[mi][nj][0] + b0, acc[mi][nj][1] + b1);
            float2 v1 = make_float2(acc[mi][nj][2] + b0, acc[mi][nj][3] + b1);
            *(float2*)(out + ((size_t)gm << 10) + gn)       = v0;
            *(float2*)(out + ((size_t)(gm + 8) << 10) + gn) = v1;
        }
    }
    #undef LOAD_CHUNK
}

// ---------------------------------------------------------------------------
extern "C" void kernel_launch(void* const* d_in, const int* in_sizes, int n_in,
                              void* d_out, int out_size)
{
    (void)in_sizes; (void)n_in; (void)out_size;
    const float* x       = (const float*)d_in[0];
    const int*   lengths = (const int*)  d_in[1];
    const float* Wk      = (const float*)d_in[2];
    const float* Wq      = (const float*)d_in[3];
    const float* Wv      = (const float*)d_in[4];
    const float* Wu      = (const float*)d_in[5];
    const float* bu      = (const float*)d_in[6];
    float* out = (float*)d_out;

    cudaFuncSetAttribute(qkv_kernel,  cudaFuncAttributeMaxDynamicSharedMemorySize,
                         QKV_SMEM_BYTES);
    cudaFuncSetAttribute(attn_kernel, cudaFuncAttributeMaxDynamicSharedMemorySize,
                         ATTN_SMEM_BYTES);
    cudaFuncSetAttribute(out_gemm_mma, cudaFuncAttributeMaxDynamicSharedMemorySize,
                         GEMM_SMEM);

    split_W_kernel<<<(EE*EE/4)/256, 256>>>(Wu);
    qkv_kernel<<<(BB*TT)/QKV_TOK, 256, QKV_SMEM_BYTES>>>(x, Wq, Wk, Wv);
    attn_kernel<<<dim3(TT/64, BB*HH), 256, ATTN_SMEM_BYTES>>>(lengths);
    split_A_kernel<<<(BB*TT*EE/4)/256, 256>>>();
    out_gemm_mma<<<dim3(EE/128, (BB*TT)/128), 256, GEMM_SMEM>>>(bu, out);
}

// round 4
// speedup vs baseline: 2.2712x; 1.8420x over previous
#include <cuda_runtime.h>
#include <cuda_bf16.h>
#include <math.h>
#include <stdint.h>

#define BB 8
#define TT 1024
#define EE 1024
#define HH 16
#define SS 64

// Scratch (device globals — no allocation allowed)
__device__ __nv_bfloat16 g_qh[BB*HH*TT*SS];
__device__ __nv_bfloat16 g_ql[BB*HH*TT*SS];
__device__ __nv_bfloat16 g_kh[BB*HH*TT*SS];
__device__ __nv_bfloat16 g_kl[BB*HH*TT*SS];
__device__ __nv_bfloat16 g_vh[BB*HH*TT*SS];
__device__ __nv_bfloat16 g_vl[BB*HH*TT*SS];
__device__ __nv_bfloat16 g_Ah[BB*TT*EE];
__device__ __nv_bfloat16 g_Al[BB*TT*EE];
__device__ __nv_bfloat16 g_Wh[EE*EE];
__device__ __nv_bfloat16 g_Wl[EE*EE];

// ---------------------------------------------------------------------------
// Helpers
// ---------------------------------------------------------------------------
__device__ __forceinline__ uint32_t smem_u32(const void* p) {
    uint32_t a;
    asm("{ .reg .u64 t; cvta.to.shared.u64 t, %1; cvt.u32.u64 %0, t; }"
        : "=r"(a) : "l"(p));
    return a;
}

#define CP16(dst, src) \
    asm volatile("cp.async.cg.shared.global [%0], [%1], 16;" :: "r"(dst), "l"(src) : "memory")

#define LDSM4(r, addr) \
    asm volatile("ldmatrix.sync.aligned.m8n8.x4.shared.b16 {%0,%1,%2,%3}, [%4];" \
        : "=r"((r)[0]), "=r"((r)[1]), "=r"((r)[2]), "=r"((r)[3]) : "r"(addr))

#define LDSM4T(r, addr) \
    asm volatile("ldmatrix.sync.aligned.m8n8.x4.trans.shared.b16 {%0,%1,%2,%3}, [%4];" \
        : "=r"((r)[0]), "=r"((r)[1]), "=r"((r)[2]), "=r"((r)[3]) : "r"(addr))

#define MMA16816(c, a, b0, b1) \
    asm volatile("mma.sync.aligned.m16n8k16.row.col.f32.bf16.bf16.f32 " \
        "{%0,%1,%2,%3}, {%4,%5,%6,%7}, {%8,%9}, {%0,%1,%2,%3};" \
        : "+f"((c)[0]), "+f"((c)[1]), "+f"((c)[2]), "+f"((c)[3]) \
        : "r"((a)[0]), "r"((a)[1]), "r"((a)[2]), "r"((a)[3]), "r"(b0), "r"(b1))

__device__ __forceinline__ uint32_t packbf(float a, float b) {
    __nv_bfloat162 t = __floats2bfloat162_rn(a, b);
    return *(uint32_t*)&t;
}
__device__ __forceinline__ float bf_lo(uint32_t u) {
    __nv_bfloat162 t = *(__nv_bfloat162*)&u;
    return __bfloat162float(__low2bfloat16(t));
}
__device__ __forceinline__ float bf_hi(uint32_t u) {
    __nv_bfloat162 t = *(__nv_bfloat162*)&u;
    return __bfloat162float(__high2bfloat16(t));
}

// ---------------------------------------------------------------------------
// Kernel 1: QKV projections (fp32 compute), writes bf16 hi/lo pairs.
// ---------------------------------------------------------------------------
#define QKV_TOK 16
#define QKV_SMEM_BYTES ((3*4096 + QKV_TOK*EE) * 4)

__global__ __launch_bounds__(256) void qkv_kernel(
    const float* __restrict__ x,
    const float* __restrict__ Wq,
    const float* __restrict__ Wk,
    const float* __restrict__ Wv)
{
    extern __shared__ float sm[];
    float* Wt = sm;
    float* xs = sm + 3*4096;

    const int tid = threadIdx.x;

    for (int idx = tid; idx < 3*4096; idx += 256) {
        int w = idx >> 12, r = idx & 4095;
        int o = r >> 6,    s = r & 63;
        const float* W = (w == 0) ? Wq : (w == 1) ? Wk : Wv;
        Wt[(w << 12) + (s << 6) + o] = W[r];
    }
    const int bt0 = blockIdx.x * QKV_TOK;
    const float4* xg = (const float4*)(x + (size_t)bt0 * EE);
    float4* xs4 = (float4*)xs;
    for (int idx = tid; idx < QKV_TOK*EE/4; idx += 256)
        xs4[idx] = xg[idx];
    __syncthreads();

    const float qkscale = 0.17677669529663687f;  // 1024^-0.25

    #pragma unroll 1
    for (int iter = 0; iter < 12; iter++) {
        int task  = iter*256 + tid;
        int chunk = task / 768;
        int quad  = task - chunk*768;
        int col   = quad << 2;
        int w     = col >> 10;
        int rem   = col & 1023;
        int h     = rem >> 6;
        int o     = rem & 63;

        float acc[4][4];
        #pragma unroll
        for (int a = 0; a < 4; a++)
            #pragma unroll
            for (int c = 0; c < 4; c++) acc[a][c] = 0.f;

        const float* wrow = Wt + (w << 12) + o;
        const float* xrow = xs + (size_t)(chunk*4)*EE + (h << 6);
        #pragma unroll
        for (int s = 0; s < 64; s++) {
            float4 wv = *(const float4*)(wrow + (s << 6));
            #pragma unroll
            for (int tk = 0; tk < 4; tk++) {
                float xv = xrow[(size_t)tk*EE + s];
                acc[tk][0] += xv * wv.x;
                acc[tk][1] += xv * wv.y;
                acc[tk][2] += xv * wv.z;
                acc[tk][3] += xv * wv.w;
            }
        }

        float scale = (w == 2) ? 1.f : qkscale;
        __nv_bfloat16* dh = (w == 0) ? g_qh : (w == 1) ? g_kh : g_vh;
        __nv_bfloat16* dl = (w == 0) ? g_ql : (w == 1) ? g_kl : g_vl;
        #pragma unroll
        for (int tk = 0; tk < 4; tk++) {
            int bt = bt0 + chunk*4 + tk;
            int b  = bt >> 10, t = bt & 1023;
            size_t base = ((((size_t)b*HH + h)*TT + t) << 6) + o;
            float v0 = acc[tk][0]*scale, v1 = acc[tk][1]*scale;
            float v2 = acc[tk][2]*scale, v3 = acc[tk][3]*scale;
            uint32_t h01 = packbf(v0, v1), h23 = packbf(v2, v3);
            uint32_t l01 = packbf(v0 - bf_lo(h01), v1 - bf_hi(h01));
            uint32_t l23 = packbf(v2 - bf_lo(h23), v3 - bf_hi(h23));
            *(uint32_t*)(dh + base)     = h01;
            *(uint32_t*)(dh + base + 2) = h23;
            *(uint32_t*)(dl + base)     = l01;
            *(uint32_t*)(dl + base + 2) = l23;
        }
    }
}

// ---------------------------------------------------------------------------
// Kernel 2: flash attention, HMMA bf16 split precision.
// CTA: 128 queries for one (b,h). 8 warps x 16 rows. Key tiles of 64.
// smem: double-buffered {Kh,Kl,Vh,Vl} tiles (64 rows x 144B pad) = 72KB.
// Q tiles staged in buffer-1 region before the loop, held in registers.
// ---------------------------------------------------------------------------
#define AT_ROWB 144
#define AT_TILE (64*AT_ROWB)          // 9216
#define AT_BUF  (4*AT_TILE)           // 36864
#define AT_SMEM (2*AT_BUF)            // 73728

__global__ __launch_bounds__(256) void attn_mma(const int* __restrict__ lengths)
{
    extern __shared__ __align__(16) char smc[];
    const uint32_t sb = smem_u32(smc);

    const int tid  = threadIdx.x;
    const int w    = tid >> 5;
    const int lane = tid & 31;
    const int qt   = blockIdx.x;        // 0..7
    const int bh   = blockIdx.y;        // 0..127
    const int q0   = qt << 7;
    const int len  = lengths[bh >> 4];

    const int l7  = lane & 7;
    const int l8  = (lane >> 3) & 1;
    const int lhi = lane >> 4;

    const size_t gbase = ((size_t)bh) << 16;   // bh * T * S

    // --- stage Q (hi/lo) into buffer-1 region, then registers ---
    #pragma unroll
    for (int i = 0; i < 4; i++) {
        int op = tid + (i << 8);
        int row = op >> 3, seg = op & 7;
        size_t src = gbase + ((size_t)(q0 + row) << 6) + (seg << 3);
        uint32_t doff = row*AT_ROWB + seg*16;
        CP16(sb + AT_BUF + doff, g_qh + src);
        CP16(sb + AT_BUF + 2*AT_TILE + doff, g_ql + src);
    }
    asm volatile("cp.async.commit_group;" ::: "memory");

    const int nkt_q = 2*(qt + 1);
    const int nkt_l = (len + 63) >> 6;
    const int nkt = nkt_q < nkt_l ? nkt_q : nkt_l;

    // --- loader for K/V tiles ---
    #define AT_LOAD(kt_, buf_) do {                                           \
        int k0_ = (kt_) << 6;                                                 \
        uint32_t base_ = sb + (buf_)*AT_BUF;                                  \
        _Pragma("unroll")                                                     \
        for (int i_ = 0; i_ < 2; i_++) {                                      \
            int op_ = tid + (i_ << 8);                                        \
            int row_ = op_ >> 3, seg_ = op_ & 7;                              \
            size_t src_ = gbase + ((size_t)(k0_ + row_) << 6) + (seg_ << 3);  \
            uint32_t doff_ = row_*AT_ROWB + seg_*16;                          \
            CP16(base_ + doff_,             g_kh + src_);                     \
            CP16(base_ + AT_TILE + doff_,   g_kl + src_);                     \
            CP16(base_ + 2*AT_TILE + doff_, g_vh + src_);                     \
            CP16(base_ + 3*AT_TILE + doff_, g_vl + src_);                     \
        }                                                                     \
        asm volatile("cp.async.commit_group;" ::: "memory");                  \
    } while (0)

    AT_LOAD(0, 0);
    asm volatile("cp.async.wait_group 1;" ::: "memory");   // Q done
    __syncthreads();

    // Q fragments (A operand, rows = this warp's 16 queries)
    uint32_t qhf[4][4], qlf[4][4];
    {
        const uint32_t qrow = (uint32_t)(16*w + l7 + 8*l8);
        #pragma unroll
        for (int ks = 0; ks < 4; ks++) {
            uint32_t boff = qrow*AT_ROWB + ks*32 + lhi*16;
            LDSM4(qhf[ks], sb + AT_BUF + boff);
            LDSM4(qlf[ks], sb + AT_BUF + 2*AT_TILE + boff);
        }
    }
    __syncthreads();   // Q reads done before buffer-1 is overwritten

    float m0 = -INFINITY, m1 = -INFINITY, l0 = 0.f, l1 = 0.f;
    float o[8][4];
    #pragma unroll
    for (int nt = 0; nt < 8; nt++)
        #pragma unroll
        for (int j = 0; j < 4; j++) o[nt][j] = 0.f;

    const int r0g = q0 + 16*w + (lane >> 2);
    const int r1g = r0g + 8;

    #pragma unroll 1
    for (int kt = 0; kt < nkt; kt++) {
        const int buf = kt & 1;
        const int k0 = kt << 6;
        if (kt + 1 < nkt) {
            AT_LOAD(kt + 1, buf ^ 1);
            asm volatile("cp.async.wait_group 1;" ::: "memory");
        } else {
            asm volatile("cp.async.wait_group 0;" ::: "memory");
        }
        __syncthreads();

        const uint32_t bKh = sb + buf*AT_BUF;
        const uint32_t bKl = bKh + AT_TILE;
        const uint32_t bVh = bKh + 2*AT_TILE;
        const uint32_t bVl = bKh + 3*AT_TILE;

        // ---- S = Qh*Kh + Ql*Kh + Qh*Kl ----
        float s[8][4];
        #pragma unroll
        for (int nt = 0; nt < 8; nt++)
            #pragma unroll
            for (int j = 0; j < 4; j++) s[nt][j] = 0.f;

        const uint32_t krow = (uint32_t)(l7 + 8*l8);
        #pragma unroll
        for (int ks = 0; ks < 4; ks++) {
            uint32_t kb[8][2];
            #pragma unroll
            for (int g = 0; g < 4; g++) {
                uint32_t r[4];
                LDSM4(r, bKh + (16*g + krow)*AT_ROWB + ks*32 + lhi*16);
                kb[2*g][0] = r[0]; kb[2*g+1][0] = r[1];
                kb[2*g][1] = r[2]; kb[2*g+1][1] = r[3];
            }
            #pragma unroll
            for (int nt = 0; nt < 8; nt++)
                MMA16816(s[nt], qhf[ks], kb[nt][0], kb[nt][1]);
            #pragma unroll
            for (int nt = 0; nt < 8; nt++)
                MMA16816(s[nt], qlf[ks], kb[nt][0], kb[nt][1]);
            #pragma unroll
            for (int g = 0; g < 4; g++) {
                uint32_t r[4];
                LDSM4(r, bKl + (16*g + krow)*AT_ROWB + ks*32 + lhi*16);
                kb[2*g][0] = r[0]; kb[2*g+1][0] = r[1];
                kb[2*g][1] = r[2]; kb[2*g+1][1] = r[3];
            }
            #pragma unroll
            for (int nt = 0; nt < 8; nt++)
                MMA16816(s[nt], qhf[ks], kb[nt][0], kb[nt][1]);
        }

        // ---- mask ----
        if (k0 + 63 > q0 + 16*w || k0 + 64 > len) {
            #pragma unroll
            for (int nt = 0; nt < 8; nt++) {
                int c0 = k0 + nt*8 + (lane & 3)*2;
                int c1 = c0 + 1;
                if (c0 > r0g || c0 >= len) s[nt][0] = -INFINITY;
                if (c1 > r0g || c1 >= len) s[nt][1] = -INFINITY;
                if (c0 > r1g || c0 >= len) s[nt][2] = -INFINITY;
                if (c1 > r1g || c1 >= len) s[nt][3] = -INFINITY;
            }
        }

        // ---- online softmax ----
        float mx0 = -INFINITY, mx1 = -INFINITY;
        #pragma unroll
        for (int nt = 0; nt < 8; nt++) {
            mx0 = fmaxf(mx0, fmaxf(s[nt][0], s[nt][1]));
            mx1 = fmaxf(mx1, fmaxf(s[nt][2], s[nt][3]));
        }
        mx0 = fmaxf(mx0, __shfl_xor_sync(0xffffffffu, mx0, 1));
        mx0 = fmaxf(mx0, __shfl_xor_sync(0xffffffffu, mx0, 2));
        mx1 = fmaxf(mx1, __shfl_xor_sync(0xffffffffu, mx1, 1));
        mx1 = fmaxf(mx1, __shfl_xor_sync(0xffffffffu, mx1, 2));

        float mn0 = fmaxf(m0, mx0), mn1 = fmaxf(m1, mx1);
        float cr0 = __expf(m0 - mn0), cr1 = __expf(m1 - mn1);
        m0 = mn0; m1 = mn1;

        float rs0 = 0.f, rs1 = 0.f;
        #pragma unroll
        for (int nt = 0; nt < 8; nt++) {
            s[nt][0] = __expf(s[nt][0] - mn0);
            s[nt][1] = __expf(s[nt][1] - mn0);
            s[nt][2] = __expf(s[nt][2] - mn1);
            s[nt][3] = __expf(s[nt][3] - mn1);
            rs0 += s[nt][0] + s[nt][1];
            rs1 += s[nt][2] + s[nt][3];
        }
        rs0 += __shfl_xor_sync(0xffffffffu, rs0, 1);
        rs0 += __shfl_xor_sync(0xffffffffu, rs0, 2);
        rs1 += __shfl_xor_sync(0xffffffffu, rs1, 1);
        rs1 += __shfl_xor_sync(0xffffffffu, rs1, 2);
        l0 = l0*cr0 + rs0;
        l1 = l1*cr1 + rs1;
        #pragma unroll
        for (int nt = 0; nt < 8; nt++) {
            o[nt][0] *= cr0; o[nt][1] *= cr0;
            o[nt][2] *= cr1; o[nt][3] *= cr1;
        }

        // ---- O += (Ph + Pl) * (Vh + Vl) [3 passes] ----
        const uint32_t vrowb = (uint32_t)(l7 + 8*l8);
        #pragma unroll
        for (int ks = 0; ks < 4; ks++) {
            uint32_t ah[4], al[4];
            ah[0] = packbf(s[2*ks][0],   s[2*ks][1]);
            ah[1] = packbf(s[2*ks][2],   s[2*ks][3]);
            ah[2] = packbf(s[2*ks+1][0], s[2*ks+1][1]);
            ah[3] = packbf(s[2*ks+1][2], s[2*ks+1][3]);
            al[0] = packbf(s[2*ks][0]   - bf_lo(ah[0]), s[2*ks][1]   - bf_hi(ah[0]));
            al[1] = packbf(s[2*ks][2]   - bf_lo(ah[1]), s[2*ks][3]   - bf_hi(ah[1]));
            al[2] = packbf(s[2*ks+1][0] - bf_lo(ah[2]), s[2*ks+1][1] - bf_hi(ah[2]));
            al[3] = packbf(s[2*ks+1][2] - bf_lo(ah[3]), s[2*ks+1][3] - bf_hi(ah[3]));

            uint32_t vb[8][2];
            #pragma unroll
            for (int g = 0; g < 4; g++) {
                uint32_t r[4];
                LDSM4T(r, bVh + (16*ks + vrowb)*AT_ROWB + g*32 + lhi*16);
                vb[2*g][0] = r[0]; vb[2*g][1] = r[1];
                vb[2*g+1][0] = r[2]; vb[2*g+1][1] = r[3];
            }
            #pragma unroll
            for (int nt = 0; nt < 8; nt++)
                MMA16816(o[nt], ah, vb[nt][0], vb[nt][1]);
            #pragma unroll
            for (int nt = 0; nt < 8; nt++)
                MMA16816(o[nt], al, vb[nt][0], vb[nt][1]);
            #pragma unroll
            for (int g = 0; g < 4; g++) {
                uint32_t r[4];
                LDSM4T(r, bVl + (16*ks + vrowb)*AT_ROWB + g*32 + lhi*16);
                vb[2*g][0] = r[0]; vb[2*g][1] = r[1];
                vb[2*g+1][0] = r[2]; vb[2*g+1][1] = r[3];
            }
            #pragma unroll
            for (int nt = 0; nt < 8; nt++)
                MMA16816(o[nt], ah, vb[nt][0], vb[nt][1]);
        }
        __syncthreads();
    }
    #undef AT_LOAD

    // ---- epilogue: normalize, split to bf16 hi/lo, write g_Ah/g_Al ----
    const float inv0 = 1.f / l0, inv1 = 1.f / l1;
    const int b = bh >> 4, h = bh & 15;
    const size_t base0 = (((size_t)b*TT + r0g) << 10) + (h << 6);
    const size_t base1 = (((size_t)b*TT + r1g) << 10) + (h << 6);
    #pragma unroll
    for (int nt = 0; nt < 8; nt++) {
        int d = nt*8 + (lane & 3)*2;
        float v0 = o[nt][0]*inv0, v1 = o[nt][1]*inv0;
        float v2 = o[nt][2]*inv1, v3 = o[nt][3]*inv1;
        uint32_t h01 = packbf(v0, v1);
        uint32_t h23 = packbf(v2, v3);
        *(uint32_t*)(g_Ah + base0 + d) = h01;
        *(uint32_t*)(g_Ah + base1 + d) = h23;
        *(uint32_t*)(g_Al + base0 + d) = packbf(v0 - bf_lo(h01), v1 - bf_hi(h01));
        *(uint32_t*)(g_Al + base1 + d) = packbf(v2 - bf_lo(h23), v3 - bf_hi(h23));
    }
}

// ---------------------------------------------------------------------------
// Split Wu fp32 -> (hi, lo) bf16.
// ---------------------------------------------------------------------------
__global__ __launch_bounds__(256) void split_W_kernel(const float* __restrict__ src)
{
    int i = blockIdx.x*256 + threadIdx.x;
    float4 v = ((const float4*)src)[i];
    float f[4] = {v.x, v.y, v.z, v.w};
    __nv_bfloat16 h[4], l[4];
    #pragma unroll
    for (int j = 0; j < 4; j++) {
        h[j] = __float2bfloat16(f[j]);
        l[j] = __float2bfloat16(f[j] - __bfloat162float(h[j]));
    }
    __nv_bfloat162* hp = (__nv_bfloat162*)g_Wh;
    __nv_bfloat162* lp = (__nv_bfloat162*)g_Wl;
    hp[i*2+0] = __nv_bfloat162(h[0], h[1]);
    hp[i*2+1] = __nv_bfloat162(h[2], h[3]);
    lp[i*2+0] = __nv_bfloat162(l[0], l[1]);
    lp[i*2+1] = __nv_bfloat162(l[2], l[3]);
}

// ---------------------------------------------------------------------------
// Kernel 3: out = A @ Wu^T + bu via mma.sync bf16 split-precision (3 passes).
// ---------------------------------------------------------------------------
#define SPAD 72
#define TILE_BYTES (128*SPAD*2)       // 18432
#define GEMM_SMEM (4*TILE_BYTES)      // 73728

__global__ __launch_bounds__(256) void out_gemm_mma(
    const float* __restrict__ bu,
    float* __restrict__ out)
{
    extern __shared__ __align__(16) char smc[];
    const uint32_t sb = smem_u32(smc);

    const int tid  = threadIdx.x;
    const int warp = tid >> 5;
    const int lane = tid & 31;
    const int m0 = blockIdx.y << 7;
    const int n0 = blockIdx.x << 7;

    const int wm = warp >> 2;
    const int wn = warp & 3;

    const int a_row = (lane & 7) + ((lane >> 3) & 1) * 8;
    const int a_kh  = (lane >> 4) * 8;
    const int b_row = (lane & 7) + ((lane >> 4) & 1) * 8;
    const int b_kh  = ((lane >> 3) & 1) * 8;

    float acc[4][4][4];
    #pragma unroll
    for (int i = 0; i < 4; i++)
        #pragma unroll
        for (int j = 0; j < 4; j++)
            #pragma unroll
            for (int q = 0; q < 4; q++) acc[i][j][q] = 0.f;

    #define LOAD_CHUNK(it_, buf_) do {                                        \
        int pass_ = (it_) >> 4, kc_ = (it_) & 15, k0_ = kc_ << 6;             \
        const __nv_bfloat16* Asrc = (pass_ == 2) ? g_Al : g_Ah;               \
        const __nv_bfloat16* Bsrc = (pass_ == 1) ? g_Wl : g_Wh;               \
        uint32_t dA = sb + (buf_) * (2*TILE_BYTES);                           \
        uint32_t dB = dA + TILE_BYTES;                                        \
        _Pragma("unroll")                                                     \
        for (int i_ = 0; i_ < 4; i_++) {                                      \
            int o_ = tid + (i_ << 8);                                         \
            int row_ = o_ >> 3, seg_ = o_ & 7;                                \
            CP16(dA + row_*144 + seg_*16,                                     \
                 Asrc + (((size_t)(m0 + row_)) << 10) + k0_ + seg_*8);        \
            CP16(dB + row_*144 + seg_*16,                                     \
                 Bsrc + (((size_t)(n0 + row_)) << 10) + k0_ + seg_*8);        \
        }                                                                     \
        asm volatile("cp.async.commit_group;" ::: "memory");                  \
    } while (0)

    LOAD_CHUNK(0, 0);

    #pragma unroll 1
    for (int it = 0; it < 48; it++) {
        const int buf = it & 1;
        if (it + 1 < 48) {
            LOAD_CHUNK(it + 1, buf ^ 1);
            asm volatile("cp.async.wait_group 1;" ::: "memory");
        } else {
            asm volatile("cp.async.wait_group 0;" ::: "memory");
        }
        __syncthreads();

        const uint32_t aBase = sb + buf * (2*TILE_BYTES);
        const uint32_t bBase = aBase + TILE_BYTES;

        #pragma unroll
        for (int ks = 0; ks < 4; ks++) {
            const int k16 = ks << 4;
            uint32_t af[4][4];
            #pragma unroll
            for (int mi = 0; mi < 4; mi++) {
                uint32_t addr = aBase +
                    (uint32_t)(((wm*64 + mi*16 + a_row) * SPAD + k16 + a_kh) * 2);
                LDSM4(af[mi], addr);
            }
            uint32_t bf[2][4];
            #pragma unroll
            for (int bj = 0; bj < 2; bj++) {
                uint32_t addr = bBase +
                    (uint32_t)(((wn*32 + bj*16 + b_row) * SPAD + k16 + b_kh) * 2);
                LDSM4(bf[bj], addr);
            }
            #pragma unroll
            for (int mi = 0; mi < 4; mi++)
                #pragma unroll
                for (int nj = 0; nj < 4; nj++) {
                    uint32_t b0 = bf[nj >> 1][(nj & 1) * 2];
                    uint32_t b1 = bf[nj >> 1][(nj & 1) * 2 + 1];
                    MMA16816(acc[mi][nj], af[mi], b0, b1);
                }
        }
        __syncthreads();
    }

    const int r0 = lane >> 2;
    const int cp = (lane & 3) * 2;
    #pragma unroll
    for (int mi = 0; mi < 4; mi++) {
        #pragma unroll
        for (int nj = 0; nj < 4; nj++) {
            int gm = m0 + wm*64 + mi*16 + r0;
            int gn = n0 + wn*32 + nj*8 + cp;
            float b0 = bu[gn], b1 = bu[gn + 1];
            float2 v0 = make_float2(acc[mi][nj][0] + b0, acc[mi][nj][1] + b1);
            float2 v1 = make_float2(acc[mi][nj][2] + b0, acc[mi][nj][3] + b1);
            *(float2*)(out + ((size_t)gm << 10) + gn)       = v0;
            *(float2*)(out + ((size_t)(gm + 8) << 10) + gn) = v1;
        }
    }
    #undef LOAD_CHUNK
}

// ---------------------------------------------------------------------------
extern "C" void kernel_launch(void* const* d_in, const int* in_sizes, int n_in,
                              void* d_out, int out_size)
{
    (void)in_sizes; (void)n_in; (void)out_size;
    const float* x       = (const float*)d_in[0];
    const int*   lengths = (const int*)  d_in[1];
    const float* Wk      = (const float*)d_in[2];
    const float* Wq      = (const float*)d_in[3];
    const float* Wv      = (const float*)d_in[4];
    const float* Wu      = (const float*)d_in[5];
    const float* bu      = (const float*)d_in[6];
    float* out = (float*)d_out;

    cudaFuncSetAttribute(qkv_kernel,  cudaFuncAttributeMaxDynamicSharedMemorySize,
                         QKV_SMEM_BYTES);
    cudaFuncSetAttribute(attn_mma, cudaFuncAttributeMaxDynamicSharedMemorySize,
                         AT_SMEM);
    cudaFuncSetAttribute(out_gemm_mma, cudaFuncAttributeMaxDynamicSharedMemorySize,
                         GEMM_SMEM);

    split_W_kernel<<<(EE*EE/4)/256, 256>>>(Wu);
    qkv_kernel<<<(BB*TT)/QKV_TOK, 256, QKV_SMEM_BYTES>>>(x, Wq, Wk, Wv);
    attn_mma<<<dim3(TT/128, BB*HH), 256, AT_SMEM>>>(lengths);
    out_gemm_mma<<<dim3(EE/128, (BB*TT)/128), 256, GEMM_SMEM>>>(bu, out);
}

// round 5
// speedup vs baseline: 2.5609x; 1.1276x over previous
#include <cuda_runtime.h>
#include <cuda_bf16.h>
#include <math.h>
#include <stdint.h>

#define BB 8
#define TT 1024
#define EE 1024
#define HH 16
#define SS 64

// Scratch (device globals — no allocation allowed)
__device__ __nv_bfloat16 g_qh[BB*HH*TT*SS];
__device__ __nv_bfloat16 g_ql[BB*HH*TT*SS];
__device__ __nv_bfloat16 g_kh[BB*HH*TT*SS];
__device__ __nv_bfloat16 g_kl[BB*HH*TT*SS];
__device__ __nv_bfloat16 g_vh[BB*HH*TT*SS];
__device__ __nv_bfloat16 g_vl[BB*HH*TT*SS];
__device__ __nv_bfloat16 g_Ah[BB*TT*EE];
__device__ __nv_bfloat16 g_Al[BB*TT*EE];
__device__ __nv_bfloat16 g_Wh[EE*EE];
__device__ __nv_bfloat16 g_Wl[EE*EE];

// ---------------------------------------------------------------------------
// Helpers
// ---------------------------------------------------------------------------
__device__ __forceinline__ uint32_t smem_u32(const void* p) {
    uint32_t a;
    asm("{ .reg .u64 t; cvta.to.shared.u64 t, %1; cvt.u32.u64 %0, t; }"
        : "=r"(a) : "l"(p));
    return a;
}

#define CP16(dst, src) \
    asm volatile("cp.async.cg.shared.global [%0], [%1], 16;" :: "r"(dst), "l"(src) : "memory")

#define LDSM4(r, addr) \
    asm volatile("ldmatrix.sync.aligned.m8n8.x4.shared.b16 {%0,%1,%2,%3}, [%4];" \
        : "=r"((r)[0]), "=r"((r)[1]), "=r"((r)[2]), "=r"((r)[3]) : "r"(addr))

#define LDSM4T(r, addr) \
    asm volatile("ldmatrix.sync.aligned.m8n8.x4.trans.shared.b16 {%0,%1,%2,%3}, [%4];" \
        : "=r"((r)[0]), "=r"((r)[1]), "=r"((r)[2]), "=r"((r)[3]) : "r"(addr))

#define MMA16816(c, a, b0, b1) \
    asm volatile("mma.sync.aligned.m16n8k16.row.col.f32.bf16.bf16.f32 " \
        "{%0,%1,%2,%3}, {%4,%5,%6,%7}, {%8,%9}, {%0,%1,%2,%3};" \
        : "+f"((c)[0]), "+f"((c)[1]), "+f"((c)[2]), "+f"((c)[3]) \
        : "r"((a)[0]), "r"((a)[1]), "r"((a)[2]), "r"((a)[3]), "r"(b0), "r"(b1))

__device__ __forceinline__ uint32_t packbf(float a, float b) {
    __nv_bfloat162 t = __floats2bfloat162_rn(a, b);
    return *(uint32_t*)&t;
}
__device__ __forceinline__ float bf_lo(uint32_t u) {
    __nv_bfloat162 t = *(__nv_bfloat162*)&u;
    return __bfloat162float(__low2bfloat16(t));
}
__device__ __forceinline__ float bf_hi(uint32_t u) {
    __nv_bfloat162 t = *(__nv_bfloat162*)&u;
    return __bfloat162float(__high2bfloat16(t));
}

// ---------------------------------------------------------------------------
// Kernel 1: QKV projections via HMMA split precision.
// x viewed as (B*T*H, 64) fp32 row-major; CTA = 128 rows, all 3 weights.
// smem: Ah/Al tiles (128 x 64 bf16, pitch 144B) + 6 weight tiles (64 x 144B).
// ---------------------------------------------------------------------------
#define QK_AH 0
#define QK_AL 18432
#define QK_W  36864              // Wq_h, Wq_l, Wk_h, Wk_l, Wv_h, Wv_l
#define QK_WT 9216               // 64*144
#define QK_SMEM 92160

__global__ __launch_bounds__(256) void qkv_mma(
    const float* __restrict__ x,
    const float* __restrict__ Wq,
    const float* __restrict__ Wk,
    const float* __restrict__ Wv)
{
    extern __shared__ __align__(16) char smc[];
    const uint32_t sb = smem_u32(smc);
    const int tid  = threadIdx.x;
    const int w    = tid >> 5;
    const int lane = tid & 31;
    const int rt0  = blockIdx.x << 7;

    // --- convert x tile to bf16 hi/lo in smem ---
    {
        int row = tid >> 1, half = tid & 1;
        const float* xr = x + ((size_t)(rt0 + row) << 6) + half*32;
        char* dh = smc + QK_AH + row*144 + half*64;
        char* dl = smc + QK_AL + row*144 + half*64;
        #pragma unroll
        for (int i = 0; i < 8; i++) {
            float4 f = *(const float4*)(xr + i*4);
            uint32_t h01 = packbf(f.x, f.y), h23 = packbf(f.z, f.w);
            uint32_t l01 = packbf(f.x - bf_lo(h01), f.y - bf_hi(h01));
            uint32_t l23 = packbf(f.z - bf_lo(h23), f.w - bf_hi(h23));
            *(uint2*)(dh + i*8) = make_uint2(h01, h23);
            *(uint2*)(dl + i*8) = make_uint2(l01, l23);
        }
    }
    // --- convert 3 weights to bf16 hi/lo tiles ---
    #pragma unroll
    for (int widx = 0; widx < 3; widx++) {
        const float* W = (widx == 0) ? Wq : (widx == 1) ? Wk : Wv;
        char* base = smc + QK_W + widx*2*QK_WT;
        #pragma unroll
        for (int i = 0; i < 4; i++) {
            int idx = tid + (i << 8);
            int o = idx >> 4, s4 = (idx & 15) << 2;
            float4 f = *(const float4*)(W + (o << 6) + s4);
            uint32_t h01 = packbf(f.x, f.y), h23 = packbf(f.z, f.w);
            uint32_t l01 = packbf(f.x - bf_lo(h01), f.y - bf_hi(h01));
            uint32_t l23 = packbf(f.z - bf_lo(h23), f.w - bf_hi(h23));
            *(uint2*)(base + o*144 + s4*2)         = make_uint2(h01, h23);
            *(uint2*)(base + QK_WT + o*144 + s4*2) = make_uint2(l01, l23);
        }
    }
    __syncthreads();

    // --- A fragments (16 rows per warp), loaded once ---
    const int a_row = (lane & 7) + ((lane >> 3) & 1) * 8;
    const int a_kh  = (lane >> 4) * 8;
    const int b_row = (lane & 7) + ((lane >> 4) & 1) * 8;
    const int b_kh  = ((lane >> 3) & 1) * 8;

    uint32_t ah[4][4], al[4][4];
    #pragma unroll
    for (int ks = 0; ks < 4; ks++) {
        uint32_t off = (uint32_t)((16*w + a_row)*144 + (ks*16 + a_kh)*2);
        LDSM4(ah[ks], sb + QK_AH + off);
        LDSM4(al[ks], sb + QK_AL + off);
    }

    const float qkscale = 0.17677669529663687f;  // 1024^-0.25
    const int r0 = lane >> 2;
    const int cp = (lane & 3) * 2;

    #pragma unroll
    for (int widx = 0; widx < 3; widx++) {
        const uint32_t bh_base = sb + QK_W + widx*2*QK_WT;
        const uint32_t bl_base = bh_base + QK_WT;

        float acc[8][4];
        #pragma unroll
        for (int nt = 0; nt < 8; nt++)
            #pragma unroll
            for (int q = 0; q < 4; q++) acc[nt][q] = 0.f;

        #pragma unroll
        for (int ks = 0; ks < 4; ks++) {
            uint32_t kb[8][2];
            #pragma unroll
            for (int g = 0; g < 4; g++) {
                uint32_t r[4];
                LDSM4(r, bh_base + (uint32_t)((16*g + b_row)*144 + (ks*16 + b_kh)*2));
                kb[2*g][0] = r[0]; kb[2*g][1] = r[1];
                kb[2*g+1][0] = r[2]; kb[2*g+1][1] = r[3];
            }
            #pragma unroll
            for (int nt = 0; nt < 8; nt++)
                MMA16816(acc[nt], ah[ks], kb[nt][0], kb[nt][1]);
            #pragma unroll
            for (int nt = 0; nt < 8; nt++)
                MMA16816(acc[nt], al[ks], kb[nt][0], kb[nt][1]);
            #pragma unroll
            for (int g = 0; g < 4; g++) {
                uint32_t r[4];
                LDSM4(r, bl_base + (uint32_t)((16*g + b_row)*144 + (ks*16 + b_kh)*2));
                kb[2*g][0] = r[0]; kb[2*g][1] = r[1];
                kb[2*g+1][0] = r[2]; kb[2*g+1][1] = r[3];
            }
            #pragma unroll
            for (int nt = 0; nt < 8; nt++)
                MMA16816(acc[nt], ah[ks], kb[nt][0], kb[nt][1]);
        }

        // --- epilogue: scale, split hi/lo, scatter to [b][h][t][s] ---
        float scale = (widx == 2) ? 1.f : qkscale;
        __nv_bfloat16* dh = (widx == 0) ? g_qh : (widx == 1) ? g_kh : g_vh;
        __nv_bfloat16* dl = (widx == 0) ? g_ql : (widx == 1) ? g_kl : g_vl;

        int gr0 = rt0 + 16*w + r0;
        int gr1 = gr0 + 8;
        // r = (b*1024 + t)*16 + h
        size_t d0 = ((((size_t)(gr0 >> 14) * HH + (gr0 & 15)) * TT + ((gr0 >> 4) & 1023)) << 6) + cp;
        size_t d1 = ((((size_t)(gr1 >> 14) * HH + (gr1 & 15)) * TT + ((gr1 >> 4) & 1023)) << 6) + cp;

        #pragma unroll
        for (int nt = 0; nt < 8; nt++) {
            float v0 = acc[nt][0]*scale, v1 = acc[nt][1]*scale;
            float v2 = acc[nt][2]*scale, v3 = acc[nt][3]*scale;
            uint32_t h01 = packbf(v0, v1), h23 = packbf(v2, v3);
            *(uint32_t*)(dh + d0 + nt*8) = h01;
            *(uint32_t*)(dh + d1 + nt*8) = h23;
            *(uint32_t*)(dl + d0 + nt*8) = packbf(v0 - bf_lo(h01), v1 - bf_hi(h01));
            *(uint32_t*)(dl + d1 + nt*8) = packbf(v2 - bf_lo(h23), v3 - bf_hi(h23));
        }
    }
}

// ---------------------------------------------------------------------------
// Kernel 2: flash attention, HMMA bf16 split precision (unchanged from R3).
// ---------------------------------------------------------------------------
#define AT_ROWB 144
#define AT_TILE (64*AT_ROWB)
#define AT_BUF  (4*AT_TILE)
#define AT_SMEM (2*AT_BUF)

__global__ __launch_bounds__(256) void attn_mma(const int* __restrict__ lengths)
{
    extern __shared__ __align__(16) char smc[];
    const uint32_t sb = smem_u32(smc);

    const int tid  = threadIdx.x;
    const int w    = tid >> 5;
    const int lane = tid & 31;
    const int qt   = blockIdx.x;
    const int bh   = blockIdx.y;
    const int q0   = qt << 7;
    const int len  = lengths[bh >> 4];

    const int l7  = lane & 7;
    const int l8  = (lane >> 3) & 1;
    const int lhi = lane >> 4;

    const size_t gbase = ((size_t)bh) << 16;

    #pragma unroll
    for (int i = 0; i < 4; i++) {
        int op = tid + (i << 8);
        int row = op >> 3, seg = op & 7;
        size_t src = gbase + ((size_t)(q0 + row) << 6) + (seg << 3);
        uint32_t doff = row*AT_ROWB + seg*16;
        CP16(sb + AT_BUF + doff, g_qh + src);
        CP16(sb + AT_BUF + 2*AT_TILE + doff, g_ql + src);
    }
    asm volatile("cp.async.commit_group;" ::: "memory");

    const int nkt_q = 2*(qt + 1);
    const int nkt_l = (len + 63) >> 6;
    const int nkt = nkt_q < nkt_l ? nkt_q : nkt_l;

    #define AT_LOAD(kt_, buf_) do {                                           \
        int k0_ = (kt_) << 6;                                                 \
        uint32_t base_ = sb + (buf_)*AT_BUF;                                  \
        _Pragma("unroll")                                                     \
        for (int i_ = 0; i_ < 2; i_++) {                                      \
            int op_ = tid + (i_ << 8);                                        \
            int row_ = op_ >> 3, seg_ = op_ & 7;                              \
            size_t src_ = gbase + ((size_t)(k0_ + row_) << 6) + (seg_ << 3);  \
            uint32_t doff_ = row_*AT_ROWB + seg_*16;                          \
            CP16(base_ + doff_,             g_kh + src_);                     \
            CP16(base_ + AT_TILE + doff_,   g_kl + src_);                     \
            CP16(base_ + 2*AT_TILE + doff_, g_vh + src_);                     \
            CP16(base_ + 3*AT_TILE + doff_, g_vl + src_);                     \
        }                                                                     \
        asm volatile("cp.async.commit_group;" ::: "memory");                  \
    } while (0)

    AT_LOAD(0, 0);
    asm volatile("cp.async.wait_group 1;" ::: "memory");
    __syncthreads();

    uint32_t qhf[4][4], qlf[4][4];
    {
        const uint32_t qrow = (uint32_t)(16*w + l7 + 8*l8);
        #pragma unroll
        for (int ks = 0; ks < 4; ks++) {
            uint32_t boff = qrow*AT_ROWB + ks*32 + lhi*16;
            LDSM4(qhf[ks], sb + AT_BUF + boff);
            LDSM4(qlf[ks], sb + AT_BUF + 2*AT_TILE + boff);
        }
    }
    __syncthreads();

    float m0 = -INFINITY, m1 = -INFINITY, l0 = 0.f, l1 = 0.f;
    float o[8][4];
    #pragma unroll
    for (int nt = 0; nt < 8; nt++)
        #pragma unroll
        for (int j = 0; j < 4; j++) o[nt][j] = 0.f;

    const int r0g = q0 + 16*w + (lane >> 2);
    const int r1g = r0g + 8;

    #pragma unroll 1
    for (int kt = 0; kt < nkt; kt++) {
        const int buf = kt & 1;
        const int k0 = kt << 6;
        if (kt + 1 < nkt) {
            AT_LOAD(kt + 1, buf ^ 1);
            asm volatile("cp.async.wait_group 1;" ::: "memory");
        } else {
            asm volatile("cp.async.wait_group 0;" ::: "memory");
        }
        __syncthreads();

        const uint32_t bKh = sb + buf*AT_BUF;
        const uint32_t bKl = bKh + AT_TILE;
        const uint32_t bVh = bKh + 2*AT_TILE;
        const uint32_t bVl = bKh + 3*AT_TILE;

        float s[8][4];
        #pragma unroll
        for (int nt = 0; nt < 8; nt++)
            #pragma unroll
            for (int j = 0; j < 4; j++) s[nt][j] = 0.f;

        const uint32_t krow = (uint32_t)(l7 + 8*l8);
        #pragma unroll
        for (int ks = 0; ks < 4; ks++) {
            uint32_t kb[8][2];
            #pragma unroll
            for (int g = 0; g < 4; g++) {
                uint32_t r[4];
                LDSM4(r, bKh + (16*g + krow)*AT_ROWB + ks*32 + lhi*16);
                kb[2*g][0] = r[0]; kb[2*g+1][0] = r[1];
                kb[2*g][1] = r[2]; kb[2*g+1][1] = r[3];
            }
            #pragma unroll
            for (int nt = 0; nt < 8; nt++)
                MMA16816(s[nt], qhf[ks], kb[nt][0], kb[nt][1]);
            #pragma unroll
            for (int nt = 0; nt < 8; nt++)
                MMA16816(s[nt], qlf[ks], kb[nt][0], kb[nt][1]);
            #pragma unroll
            for (int g = 0; g < 4; g++) {
                uint32_t r[4];
                LDSM4(r, bKl + (16*g + krow)*AT_ROWB + ks*32 + lhi*16);
                kb[2*g][0] = r[0]; kb[2*g+1][0] = r[1];
                kb[2*g][1] = r[2]; kb[2*g+1][1] = r[3];
            }
            #pragma unroll
            for (int nt = 0; nt < 8; nt++)
                MMA16816(s[nt], qhf[ks], kb[nt][0], kb[nt][1]);
        }

        if (k0 + 63 > q0 + 16*w || k0 + 64 > len) {
            #pragma unroll
            for (int nt = 0; nt < 8; nt++) {
                int c0 = k0 + nt*8 + (lane & 3)*2;
                int c1 = c0 + 1;
                if (c0 > r0g || c0 >= len) s[nt][0] = -INFINITY;
                if (c1 > r0g || c1 >= len) s[nt][1] = -INFINITY;
                if (c0 > r1g || c0 >= len) s[nt][2] = -INFINITY;
                if (c1 > r1g || c1 >= len) s[nt][3] = -INFINITY;
            }
        }

        float mx0 = -INFINITY, mx1 = -INFINITY;
        #pragma unroll
        for (int nt = 0; nt < 8; nt++) {
            mx0 = fmaxf(mx0, fmaxf(s[nt][0], s[nt][1]));
            mx1 = fmaxf(mx1, fmaxf(s[nt][2], s[nt][3]));
        }
        mx0 = fmaxf(mx0, __shfl_xor_sync(0xffffffffu, mx0, 1));
        mx0 = fmaxf(mx0, __shfl_xor_sync(0xffffffffu, mx0, 2));
        mx1 = fmaxf(mx1, __shfl_xor_sync(0xffffffffu, mx1, 1));
        mx1 = fmaxf(mx1, __shfl_xor_sync(0xffffffffu, mx1, 2));

        float mn0 = fmaxf(m0, mx0), mn1 = fmaxf(m1, mx1);
        float cr0 = __expf(m0 - mn0), cr1 = __expf(m1 - mn1);
        m0 = mn0; m1 = mn1;

        float rs0 = 0.f, rs1 = 0.f;
        #pragma unroll
        for (int nt = 0; nt < 8; nt++) {
            s[nt][0] = __expf(s[nt][0] - mn0);
            s[nt][1] = __expf(s[nt][1] - mn0);
            s[nt][2] = __expf(s[nt][2] - mn1);
            s[nt][3] = __expf(s[nt][3] - mn1);
            rs0 += s[nt][0] + s[nt][1];
            rs1 += s[nt][2] + s[nt][3];
        }
        rs0 += __shfl_xor_sync(0xffffffffu, rs0, 1);
        rs0 += __shfl_xor_sync(0xffffffffu, rs0, 2);
        rs1 += __shfl_xor_sync(0xffffffffu, rs1, 1);
        rs1 += __shfl_xor_sync(0xffffffffu, rs1, 2);
        l0 = l0*cr0 + rs0;
        l1 = l1*cr1 + rs1;
        #pragma unroll
        for (int nt = 0; nt < 8; nt++) {
            o[nt][0] *= cr0; o[nt][1] *= cr0;
            o[nt][2] *= cr1; o[nt][3] *= cr1;
        }

        const uint32_t vrowb = (uint32_t)(l7 + 8*l8);
        #pragma unroll
        for (int ks = 0; ks < 4; ks++) {
            uint32_t ah[4], al[4];
            ah[0] = packbf(s[2*ks][0],   s[2*ks][1]);
            ah[1] = packbf(s[2*ks][2],   s[2*ks][3]);
            ah[2] = packbf(s[2*ks+1][0], s[2*ks+1][1]);
            ah[3] = packbf(s[2*ks+1][2], s[2*ks+1][3]);
            al[0] = packbf(s[2*ks][0]   - bf_lo(ah[0]), s[2*ks][1]   - bf_hi(ah[0]));
            al[1] = packbf(s[2*ks][2]   - bf_lo(ah[1]), s[2*ks][3]   - bf_hi(ah[1]));
            al[2] = packbf(s[2*ks+1][0] - bf_lo(ah[2]), s[2*ks+1][1] - bf_hi(ah[2]));
            al[3] = packbf(s[2*ks+1][2] - bf_lo(ah[3]), s[2*ks+1][3] - bf_hi(ah[3]));

            uint32_t vb[8][2];
            #pragma unroll
            for (int g = 0; g < 4; g++) {
                uint32_t r[4];
                LDSM4T(r, bVh + (16*ks + vrowb)*AT_ROWB + g*32 + lhi*16);
                vb[2*g][0] = r[0]; vb[2*g][1] = r[1];
                vb[2*g+1][0] = r[2]; vb[2*g+1][1] = r[3];
            }
            #pragma unroll
            for (int nt = 0; nt < 8; nt++)
                MMA16816(o[nt], ah, vb[nt][0], vb[nt][1]);
            #pragma unroll
            for (int nt = 0; nt < 8; nt++)
                MMA16816(o[nt], al, vb[nt][0], vb[nt][1]);
            #pragma unroll
            for (int g = 0; g < 4; g++) {
                uint32_t r[4];
                LDSM4T(r, bVl + (16*ks + vrowb)*AT_ROWB + g*32 + lhi*16);
                vb[2*g][0] = r[0]; vb[2*g][1] = r[1];
                vb[2*g+1][0] = r[2]; vb[2*g+1][1] = r[3];
            }
            #pragma unroll
            for (int nt = 0; nt < 8; nt++)
                MMA16816(o[nt], ah, vb[nt][0], vb[nt][1]);
        }
        __syncthreads();
    }
    #undef AT_LOAD

    const float inv0 = 1.f / l0, inv1 = 1.f / l1;
    const int b = bh >> 4, h = bh & 15;
    const size_t base0 = (((size_t)b*TT + r0g) << 10) + (h << 6);
    const size_t base1 = (((size_t)b*TT + r1g) << 10) + (h << 6);
    #pragma unroll
    for (int nt = 0; nt < 8; nt++) {
        int d = nt*8 + (lane & 3)*2;
        float v0 = o[nt][0]*inv0, v1 = o[nt][1]*inv0;
        float v2 = o[nt][2]*inv1, v3 = o[nt][3]*inv1;
        uint32_t h01 = packbf(v0, v1);
        uint32_t h23 = packbf(v2, v3);
        *(uint32_t*)(g_Ah + base0 + d) = h01;
        *(uint32_t*)(g_Ah + base1 + d) = h23;
        *(uint32_t*)(g_Al + base0 + d) = packbf(v0 - bf_lo(h01), v1 - bf_hi(h01));
        *(uint32_t*)(g_Al + base1 + d) = packbf(v2 - bf_lo(h23), v3 - bf_hi(h23));
    }
}

// ---------------------------------------------------------------------------
// Split Wu fp32 -> (hi, lo) bf16.
// ---------------------------------------------------------------------------
__global__ __launch_bounds__(256) void split_W_kernel(const float* __restrict__ src)
{
    int i = blockIdx.x*256 + threadIdx.x;
    float4 v = ((const float4*)src)[i];
    float f[4] = {v.x, v.y, v.z, v.w};
    __nv_bfloat16 h[4], l[4];
    #pragma unroll
    for (int j = 0; j < 4; j++) {
        h[j] = __float2bfloat16(f[j]);
        l[j] = __float2bfloat16(f[j] - __bfloat162float(h[j]));
    }
    __nv_bfloat162* hp = (__nv_bfloat162*)g_Wh;
    __nv_bfloat162* lp = (__nv_bfloat162*)g_Wl;
    hp[i*2+0] = __nv_bfloat162(h[0], h[1]);
    hp[i*2+1] = __nv_bfloat162(h[2], h[3]);
    lp[i*2+0] = __nv_bfloat162(l[0], l[1]);
    lp[i*2+1] = __nv_bfloat162(l[2], l[3]);
}

// ---------------------------------------------------------------------------
// Kernel 3: out = A @ Wu^T + bu via mma.sync bf16 split-precision (3 passes).
// CTA tile 256(M) x 128(N), 512 threads (16 warps, 4m x 4n), warp tile 64x32.
// ---------------------------------------------------------------------------
#define SPAD 72
#define ATILE_B (256*SPAD*2)      // 36864
#define BTILE_B (128*SPAD*2)      // 18432
#define GBUF (ATILE_B + BTILE_B)  // 55296
#define GEMM_SMEM (2*GBUF)        // 110592

__global__ __launch_bounds__(512, 1) void out_gemm_mma(
    const float* __restrict__ bu,
    float* __restrict__ out)
{
    extern __shared__ __align__(16) char smc[];
    const uint32_t sb = smem_u32(smc);

    const int tid  = threadIdx.x;
    const int warp = tid >> 5;
    const int lane = tid & 31;
    const int m0 = blockIdx.y << 8;
    const int n0 = blockIdx.x << 7;

    const int wm = warp >> 2;          // 0..3 -> m offset wm*64
    const int wn = warp & 3;           // 0..3 -> n offset wn*32

    const int a_row = (lane & 7) + ((lane >> 3) & 1) * 8;
    const int a_kh  = (lane >> 4) * 8;
    const int b_row = (lane & 7) + ((lane >> 4) & 1) * 8;
    const int b_kh  = ((lane >> 3) & 1) * 8;

    float acc[4][4][4];
    #pragma unroll
    for (int i = 0; i < 4; i++)
        #pragma unroll
        for (int j = 0; j < 4; j++)
            #pragma unroll
            for (int q = 0; q < 4; q++) acc[i][j][q] = 0.f;

    #define LOAD_CHUNK(it_, buf_) do {                                        \
        int pass_ = (it_) >> 4, kc_ = (it_) & 15, k0_ = kc_ << 6;             \
        const __nv_bfloat16* Asrc = (pass_ == 2) ? g_Al : g_Ah;               \
        const __nv_bfloat16* Bsrc = (pass_ == 1) ? g_Wl : g_Wh;               \
        uint32_t dA = sb + (buf_) * GBUF;                                     \
        uint32_t dB = dA + ATILE_B;                                           \
        _Pragma("unroll")                                                     \
        for (int i_ = 0; i_ < 4; i_++) {                                      \
            int o_ = tid + (i_ << 9);                                         \
            int row_ = o_ >> 3, seg_ = o_ & 7;                                \
            CP16(dA + row_*144 + seg_*16,                                     \
                 Asrc + (((size_t)(m0 + row_)) << 10) + k0_ + seg_*8);        \
        }                                                                     \
        _Pragma("unroll")                                                     \
        for (int i_ = 0; i_ < 2; i_++) {                                      \
            int o_ = tid + (i_ << 9);                                         \
            int row_ = o_ >> 3, seg_ = o_ & 7;                                \
            CP16(dB + row_*144 + seg_*16,                                     \
                 Bsrc + (((size_t)(n0 + row_)) << 10) + k0_ + seg_*8);        \
        }                                                                     \
        asm volatile("cp.async.commit_group;" ::: "memory");                  \
    } while (0)

    LOAD_CHUNK(0, 0);

    #pragma unroll 1
    for (int it = 0; it < 48; it++) {
        const int buf = it & 1;
        if (it + 1 < 48) {
            LOAD_CHUNK(it + 1, buf ^ 1);
            asm volatile("cp.async.wait_group 1;" ::: "memory");
        } else {
            asm volatile("cp.async.wait_group 0;" ::: "memory");
        }
        __syncthreads();

        const uint32_t aBase = sb + buf * GBUF;
        const uint32_t bBase = aBase + ATILE_B;

        #pragma unroll
        for (int ks = 0; ks < 4; ks++) {
            const int k16 = ks << 4;
            uint32_t af[4][4];
            #pragma unroll
            for (int mi = 0; mi < 4; mi++) {
                uint32_t addr = aBase +
                    (uint32_t)(((wm*64 + mi*16 + a_row) * SPAD + k16 + a_kh) * 2);
                LDSM4(af[mi], addr);
            }
            uint32_t bf[2][4];
            #pragma unroll
            for (int bj = 0; bj < 2; bj++) {
                uint32_t addr = bBase +
                    (uint32_t)(((wn*32 + bj*16 + b_row) * SPAD + k16 + b_kh) * 2);
                LDSM4(bf[bj], addr);
            }
            #pragma unroll
            for (int mi = 0; mi < 4; mi++)
                #pragma unroll
                for (int nj = 0; nj < 4; nj++) {
                    uint32_t b0 = bf[nj >> 1][(nj & 1) * 2];
                    uint32_t b1 = bf[nj >> 1][(nj & 1) * 2 + 1];
                    MMA16816(acc[mi][nj], af[mi], b0, b1);
                }
        }
        __syncthreads();
    }

    const int r0 = lane >> 2;
    const int cp = (lane & 3) * 2;
    #pragma unroll
    for (int mi = 0; mi < 4; mi++) {
        #pragma unroll
        for (int nj = 0; nj < 4; nj++) {
            int gm = m0 + wm*64 + mi*16 + r0;
            int gn = n0 + wn*32 + nj*8 + cp;
            float b0 = bu[gn], b1 = bu[gn + 1];
            float2 v0 = make_float2(acc[mi][nj][0] + b0, acc[mi][nj][1] + b1);
            float2 v1 = make_float2(acc[mi][nj][2] + b0, acc[mi][nj][3] + b1);
            *(float2*)(out + ((size_t)gm << 10) + gn)       = v0;
            *(float2*)(out + ((size_t)(gm + 8) << 10) + gn) = v1;
        }
    }
    #undef LOAD_CHUNK
}

// ---------------------------------------------------------------------------
extern "C" void kernel_launch(void* const* d_in, const int* in_sizes, int n_in,
                              void* d_out, int out_size)
{
    (void)in_sizes; (void)n_in; (void)out_size;
    const float* x       = (const float*)d_in[0];
    const int*   lengths = (const int*)  d_in[1];
    const float* Wk      = (const float*)d_in[2];
    const float* Wq      = (const float*)d_in[3];
    const float* Wv      = (const float*)d_in[4];
    const float* Wu      = (const float*)d_in[5];
    const float* bu      = (const float*)d_in[6];
    float* out = (float*)d_out;

    cudaFuncSetAttribute(qkv_mma, cudaFuncAttributeMaxDynamicSharedMemorySize,
                         QK_SMEM);
    cudaFuncSetAttribute(attn_mma, cudaFuncAttributeMaxDynamicSharedMemorySize,
                         AT_SMEM);
    cudaFuncSetAttribute(out_gemm_mma, cudaFuncAttributeMaxDynamicSharedMemorySize,
                         GEMM_SMEM);

    split_W_kernel<<<(EE*EE/4)/256, 256>>>(Wu);
    qkv_mma<<<(BB*TT*HH)/128, 256, QK_SMEM>>>(x, Wq, Wk, Wv);
    attn_mma<<<dim3(TT/128, BB*HH), 256, AT_SMEM>>>(lengths);
    out_gemm_mma<<<dim3(EE/128, (BB*TT)/256), 512, GEMM_SMEM>>>(bu, out);
}

// round 6
// speedup vs baseline: 2.7113x; 1.0587x over previous
#include <cuda_runtime.h>
#include <cuda_bf16.h>
#include <math.h>
#include <stdint.h>

#define BB 8
#define TT 1024
#define EE 1024
#define HH 16
#define SS 64

// Scratch (device globals — no allocation allowed)
__device__ __nv_bfloat16 g_qh[BB*HH*TT*SS];
__device__ __nv_bfloat16 g_ql[BB*HH*TT*SS];
__device__ __nv_bfloat16 g_kh[BB*HH*TT*SS];
__device__ __nv_bfloat16 g_kl[BB*HH*TT*SS];
__device__ __nv_bfloat16 g_vh[BB*HH*TT*SS];
__device__ __nv_bfloat16 g_vl[BB*HH*TT*SS];
__device__ __nv_bfloat16 g_Ah[BB*TT*EE];
__device__ __nv_bfloat16 g_Al[BB*TT*EE];
__device__ __nv_bfloat16 g_Wh[EE*EE];
__device__ __nv_bfloat16 g_Wl[EE*EE];

// ---------------------------------------------------------------------------
// Helpers
// ---------------------------------------------------------------------------
__device__ __forceinline__ uint32_t smem_u32(const void* p) {
    uint32_t a;
    asm("{ .reg .u64 t; cvta.to.shared.u64 t, %1; cvt.u32.u64 %0, t; }"
        : "=r"(a) : "l"(p));
    return a;
}

#define CP16(dst, src) \
    asm volatile("cp.async.cg.shared.global [%0], [%1], 16;" :: "r"(dst), "l"(src) : "memory")

#define LDSM4(r, addr) \
    asm volatile("ldmatrix.sync.aligned.m8n8.x4.shared.b16 {%0,%1,%2,%3}, [%4];" \
        : "=r"((r)[0]), "=r"((r)[1]), "=r"((r)[2]), "=r"((r)[3]) : "r"(addr))

#define LDSM4T(r, addr) \
    asm volatile("ldmatrix.sync.aligned.m8n8.x4.trans.shared.b16 {%0,%1,%2,%3}, [%4];" \
        : "=r"((r)[0]), "=r"((r)[1]), "=r"((r)[2]), "=r"((r)[3]) : "r"(addr))

#define MMA16816(c, a, b0, b1) \
    asm volatile("mma.sync.aligned.m16n8k16.row.col.f32.bf16.bf16.f32 " \
        "{%0,%1,%2,%3}, {%4,%5,%6,%7}, {%8,%9}, {%0,%1,%2,%3};" \
        : "+f"((c)[0]), "+f"((c)[1]), "+f"((c)[2]), "+f"((c)[3]) \
        : "r"((a)[0]), "r"((a)[1]), "r"((a)[2]), "r"((a)[3]), "r"(b0), "r"(b1))

__device__ __forceinline__ uint32_t packbf(float a, float b) {
    __nv_bfloat162 t = __floats2bfloat162_rn(a, b);
    return *(uint32_t*)&t;
}
__device__ __forceinline__ float bf_lo(uint32_t u) {
    __nv_bfloat162 t = *(__nv_bfloat162*)&u;
    return __bfloat162float(__low2bfloat16(t));
}
__device__ __forceinline__ float bf_hi(uint32_t u) {
    __nv_bfloat162 t = *(__nv_bfloat162*)&u;
    return __bfloat162float(__high2bfloat16(t));
}

// ---------------------------------------------------------------------------
// Kernel 1: QKV projections via HMMA split precision (unchanged from R4).
// ---------------------------------------------------------------------------
#define QK_AH 0
#define QK_AL 18432
#define QK_W  36864
#define QK_WT 9216
#define QK_SMEM 92160

__global__ __launch_bounds__(256) void qkv_mma(
    const float* __restrict__ x,
    const float* __restrict__ Wq,
    const float* __restrict__ Wk,
    const float* __restrict__ Wv)
{
    extern __shared__ __align__(16) char smc[];
    const uint32_t sb = smem_u32(smc);
    const int tid  = threadIdx.x;
    const int w    = tid >> 5;
    const int lane = tid & 31;
    const int rt0  = blockIdx.x << 7;

    {
        int row = tid >> 1, half = tid & 1;
        const float* xr = x + ((size_t)(rt0 + row) << 6) + half*32;
        char* dh = smc + QK_AH + row*144 + half*64;
        char* dl = smc + QK_AL + row*144 + half*64;
        #pragma unroll
        for (int i = 0; i < 8; i++) {
            float4 f = *(const float4*)(xr + i*4);
            uint32_t h01 = packbf(f.x, f.y), h23 = packbf(f.z, f.w);
            uint32_t l01 = packbf(f.x - bf_lo(h01), f.y - bf_hi(h01));
            uint32_t l23 = packbf(f.z - bf_lo(h23), f.w - bf_hi(h23));
            *(uint2*)(dh + i*8) = make_uint2(h01, h23);
            *(uint2*)(dl + i*8) = make_uint2(l01, l23);
        }
    }
    #pragma unroll
    for (int widx = 0; widx < 3; widx++) {
        const float* W = (widx == 0) ? Wq : (widx == 1) ? Wk : Wv;
        char* base = smc + QK_W + widx*2*QK_WT;
        #pragma unroll
        for (int i = 0; i < 4; i++) {
            int idx = tid + (i << 8);
            int o = idx >> 4, s4 = (idx & 15) << 2;
            float4 f = *(const float4*)(W + (o << 6) + s4);
            uint32_t h01 = packbf(f.x, f.y), h23 = packbf(f.z, f.w);
            uint32_t l01 = packbf(f.x - bf_lo(h01), f.y - bf_hi(h01));
            uint32_t l23 = packbf(f.z - bf_lo(h23), f.w - bf_hi(h23));
            *(uint2*)(base + o*144 + s4*2)         = make_uint2(h01, h23);
            *(uint2*)(base + QK_WT + o*144 + s4*2) = make_uint2(l01, l23);
        }
    }
    __syncthreads();

    const int a_row = (lane & 7) + ((lane >> 3) & 1) * 8;
    const int a_kh  = (lane >> 4) * 8;
    const int b_row = (lane & 7) + ((lane >> 4) & 1) * 8;
    const int b_kh  = ((lane >> 3) & 1) * 8;

    uint32_t ah[4][4], al[4][4];
    #pragma unroll
    for (int ks = 0; ks < 4; ks++) {
        uint32_t off = (uint32_t)((16*w + a_row)*144 + (ks*16 + a_kh)*2);
        LDSM4(ah[ks], sb + QK_AH + off);
        LDSM4(al[ks], sb + QK_AL + off);
    }

    const float qkscale = 0.17677669529663687f;
    const int r0 = lane >> 2;
    const int cp = (lane & 3) * 2;

    #pragma unroll
    for (int widx = 0; widx < 3; widx++) {
        const uint32_t bh_base = sb + QK_W + widx*2*QK_WT;
        const uint32_t bl_base = bh_base + QK_WT;

        float acc[8][4];
        #pragma unroll
        for (int nt = 0; nt < 8; nt++)
            #pragma unroll
            for (int q = 0; q < 4; q++) acc[nt][q] = 0.f;

        #pragma unroll
        for (int ks = 0; ks < 4; ks++) {
            uint32_t kb[8][2];
            #pragma unroll
            for (int g = 0; g < 4; g++) {
                uint32_t r[4];
                LDSM4(r, bh_base + (uint32_t)((16*g + b_row)*144 + (ks*16 + b_kh)*2));
                kb[2*g][0] = r[0]; kb[2*g][1] = r[1];
                kb[2*g+1][0] = r[2]; kb[2*g+1][1] = r[3];
            }
            #pragma unroll
            for (int nt = 0; nt < 8; nt++)
                MMA16816(acc[nt], ah[ks], kb[nt][0], kb[nt][1]);
            #pragma unroll
            for (int nt = 0; nt < 8; nt++)
                MMA16816(acc[nt], al[ks], kb[nt][0], kb[nt][1]);
            #pragma unroll
            for (int g = 0; g < 4; g++) {
                uint32_t r[4];
                LDSM4(r, bl_base + (uint32_t)((16*g + b_row)*144 + (ks*16 + b_kh)*2));
                kb[2*g][0] = r[0]; kb[2*g][1] = r[1];
                kb[2*g+1][0] = r[2]; kb[2*g+1][1] = r[3];
            }
            #pragma unroll
            for (int nt = 0; nt < 8; nt++)
                MMA16816(acc[nt], ah[ks], kb[nt][0], kb[nt][1]);
        }

        float scale = (widx == 2) ? 1.f : qkscale;
        __nv_bfloat16* dh = (widx == 0) ? g_qh : (widx == 1) ? g_kh : g_vh;
        __nv_bfloat16* dl = (widx == 0) ? g_ql : (widx == 1) ? g_kl : g_vl;

        int gr0 = rt0 + 16*w + r0;
        int gr1 = gr0 + 8;
        size_t d0 = ((((size_t)(gr0 >> 14) * HH + (gr0 & 15)) * TT + ((gr0 >> 4) & 1023)) << 6) + cp;
        size_t d1 = ((((size_t)(gr1 >> 14) * HH + (gr1 & 15)) * TT + ((gr1 >> 4) & 1023)) << 6) + cp;

        #pragma unroll
        for (int nt = 0; nt < 8; nt++) {
            float v0 = acc[nt][0]*scale, v1 = acc[nt][1]*scale;
            float v2 = acc[nt][2]*scale, v3 = acc[nt][3]*scale;
            uint32_t h01 = packbf(v0, v1), h23 = packbf(v2, v3);
            *(uint32_t*)(dh + d0 + nt*8) = h01;
            *(uint32_t*)(dh + d1 + nt*8) = h23;
            *(uint32_t*)(dl + d0 + nt*8) = packbf(v0 - bf_lo(h01), v1 - bf_hi(h01));
            *(uint32_t*)(dl + d1 + nt*8) = packbf(v2 - bf_lo(h23), v3 - bf_hi(h23));
        }
    }
}

// ---------------------------------------------------------------------------
// Kernel 2: flash attention, HMMA bf16 split precision (unchanged from R3).
// ---------------------------------------------------------------------------
#define AT_ROWB 144
#define AT_TILE (64*AT_ROWB)
#define AT_BUF  (4*AT_TILE)
#define AT_SMEM (2*AT_BUF)

__global__ __launch_bounds__(256) void attn_mma(const int* __restrict__ lengths)
{
    extern __shared__ __align__(16) char smc[];
    const uint32_t sb = smem_u32(smc);

    const int tid  = threadIdx.x;
    const int w    = tid >> 5;
    const int lane = tid & 31;
    const int qt   = blockIdx.x;
    const int bh   = blockIdx.y;
    const int q0   = qt << 7;
    const int len  = lengths[bh >> 4];

    const int l7  = lane & 7;
    const int l8  = (lane >> 3) & 1;
    const int lhi = lane >> 4;

    const size_t gbase = ((size_t)bh) << 16;

    #pragma unroll
    for (int i = 0; i < 4; i++) {
        int op = tid + (i << 8);
        int row = op >> 3, seg = op & 7;
        size_t src = gbase + ((size_t)(q0 + row) << 6) + (seg << 3);
        uint32_t doff = row*AT_ROWB + seg*16;
        CP16(sb + AT_BUF + doff, g_qh + src);
        CP16(sb + AT_BUF + 2*AT_TILE + doff, g_ql + src);
    }
    asm volatile("cp.async.commit_group;" ::: "memory");

    const int nkt_q = 2*(qt + 1);
    const int nkt_l = (len + 63) >> 6;
    const int nkt = nkt_q < nkt_l ? nkt_q : nkt_l;

    #define AT_LOAD(kt_, buf_) do {                                           \
        int k0_ = (kt_) << 6;                                                 \
        uint32_t base_ = sb + (buf_)*AT_BUF;                                  \
        _Pragma("unroll")                                                     \
        for (int i_ = 0; i_ < 2; i_++) {                                      \
            int op_ = tid + (i_ << 8);                                        \
            int row_ = op_ >> 3, seg_ = op_ & 7;                              \
            size_t src_ = gbase + ((size_t)(k0_ + row_) << 6) + (seg_ << 3);  \
            uint32_t doff_ = row_*AT_ROWB + seg_*16;                          \
            CP16(base_ + doff_,             g_kh + src_);                     \
            CP16(base_ + AT_TILE + doff_,   g_kl + src_);                     \
            CP16(base_ + 2*AT_TILE + doff_, g_vh + src_);                     \
            CP16(base_ + 3*AT_TILE + doff_, g_vl + src_);                     \
        }                                                                     \
        asm volatile("cp.async.commit_group;" ::: "memory");                  \
    } while (0)

    AT_LOAD(0, 0);
    asm volatile("cp.async.wait_group 1;" ::: "memory");
    __syncthreads();

    uint32_t qhf[4][4], qlf[4][4];
    {
        const uint32_t qrow = (uint32_t)(16*w + l7 + 8*l8);
        #pragma unroll
        for (int ks = 0; ks < 4; ks++) {
            uint32_t boff = qrow*AT_ROWB + ks*32 + lhi*16;
            LDSM4(qhf[ks], sb + AT_BUF + boff);
            LDSM4(qlf[ks], sb + AT_BUF + 2*AT_TILE + boff);
        }
    }
    __syncthreads();

    float m0 = -INFINITY, m1 = -INFINITY, l0 = 0.f, l1 = 0.f;
    float o[8][4];
    #pragma unroll
    for (int nt = 0; nt < 8; nt++)
        #pragma unroll
        for (int j = 0; j < 4; j++) o[nt][j] = 0.f;

    const int r0g = q0 + 16*w + (lane >> 2);
    const int r1g = r0g + 8;

    #pragma unroll 1
    for (int kt = 0; kt < nkt; kt++) {
        const int buf = kt & 1;
        const int k0 = kt << 6;
        if (kt + 1 < nkt) {
            AT_LOAD(kt + 1, buf ^ 1);
            asm volatile("cp.async.wait_group 1;" ::: "memory");
        } else {
            asm volatile("cp.async.wait_group 0;" ::: "memory");
        }
        __syncthreads();

        const uint32_t bKh = sb + buf*AT_BUF;
        const uint32_t bKl = bKh + AT_TILE;
        const uint32_t bVh = bKh + 2*AT_TILE;
        const uint32_t bVl = bKh + 3*AT_TILE;

        float s[8][4];
        #pragma unroll
        for (int nt = 0; nt < 8; nt++)
            #pragma unroll
            for (int j = 0; j < 4; j++) s[nt][j] = 0.f;

        const uint32_t krow = (uint32_t)(l7 + 8*l8);
        #pragma unroll
        for (int ks = 0; ks < 4; ks++) {
            uint32_t kb[8][2];
            #pragma unroll
            for (int g = 0; g < 4; g++) {
                uint32_t r[4];
                LDSM4(r, bKh + (16*g + krow)*AT_ROWB + ks*32 + lhi*16);
                kb[2*g][0] = r[0]; kb[2*g+1][0] = r[1];
                kb[2*g][1] = r[2]; kb[2*g+1][1] = r[3];
            }
            #pragma unroll
            for (int nt = 0; nt < 8; nt++)
                MMA16816(s[nt], qhf[ks], kb[nt][0], kb[nt][1]);
            #pragma unroll
            for (int nt = 0; nt < 8; nt++)
                MMA16816(s[nt], qlf[ks], kb[nt][0], kb[nt][1]);
            #pragma unroll
            for (int g = 0; g < 4; g++) {
                uint32_t r[4];
                LDSM4(r, bKl + (16*g + krow)*AT_ROWB + ks*32 + lhi*16);
                kb[2*g][0] = r[0]; kb[2*g+1][0] = r[1];
                kb[2*g][1] = r[2]; kb[2*g+1][1] = r[3];
            }
            #pragma unroll
            for (int nt = 0; nt < 8; nt++)
                MMA16816(s[nt], qhf[ks], kb[nt][0], kb[nt][1]);
        }

        if (k0 + 63 > q0 + 16*w || k0 + 64 > len) {
            #pragma unroll
            for (int nt = 0; nt < 8; nt++) {
                int c0 = k0 + nt*8 + (lane & 3)*2;
                int c1 = c0 + 1;
                if (c0 > r0g || c0 >= len) s[nt][0] = -INFINITY;
                if (c1 > r0g || c1 >= len) s[nt][1] = -INFINITY;
                if (c0 > r1g || c0 >= len) s[nt][2] = -INFINITY;
                if (c1 > r1g || c1 >= len) s[nt][3] = -INFINITY;
            }
        }

        float mx0 = -INFINITY, mx1 = -INFINITY;
        #pragma unroll
        for (int nt = 0; nt < 8; nt++) {
            mx0 = fmaxf(mx0, fmaxf(s[nt][0], s[nt][1]));
            mx1 = fmaxf(mx1, fmaxf(s[nt][2], s[nt][3]));
        }
        mx0 = fmaxf(mx0, __shfl_xor_sync(0xffffffffu, mx0, 1));
        mx0 = fmaxf(mx0, __shfl_xor_sync(0xffffffffu, mx0, 2));
        mx1 = fmaxf(mx1, __shfl_xor_sync(0xffffffffu, mx1, 1));
        mx1 = fmaxf(mx1, __shfl_xor_sync(0xffffffffu, mx1, 2));

        float mn0 = fmaxf(m0, mx0), mn1 = fmaxf(m1, mx1);
        float cr0 = __expf(m0 - mn0), cr1 = __expf(m1 - mn1);
        m0 = mn0; m1 = mn1;

        float rs0 = 0.f, rs1 = 0.f;
        #pragma unroll
        for (int nt = 0; nt < 8; nt++) {
            s[nt][0] = __expf(s[nt][0] - mn0);
            s[nt][1] = __expf(s[nt][1] - mn0);
            s[nt][2] = __expf(s[nt][2] - mn1);
            s[nt][3] = __expf(s[nt][3] - mn1);
            rs0 += s[nt][0] + s[nt][1];
            rs1 += s[nt][2] + s[nt][3];
        }
        rs0 += __shfl_xor_sync(0xffffffffu, rs0, 1);
        rs0 += __shfl_xor_sync(0xffffffffu, rs0, 2);
        rs1 += __shfl_xor_sync(0xffffffffu, rs1, 1);
        rs1 += __shfl_xor_sync(0xffffffffu, rs1, 2);
        l0 = l0*cr0 + rs0;
        l1 = l1*cr1 + rs1;
        #pragma unroll
        for (int nt = 0; nt < 8; nt++) {
            o[nt][0] *= cr0; o[nt][1] *= cr0;
            o[nt][2] *= cr1; o[nt][3] *= cr1;
        }

        const uint32_t vrowb = (uint32_t)(l7 + 8*l8);
        #pragma unroll
        for (int ks = 0; ks < 4; ks++) {
            uint32_t ah[4], al[4];
            ah[0] = packbf(s[2*ks][0],   s[2*ks][1]);
            ah[1] = packbf(s[2*ks][2],   s[2*ks][3]);
            ah[2] = packbf(s[2*ks+1][0], s[2*ks+1][1]);
            ah[3] = packbf(s[2*ks+1][2], s[2*ks+1][3]);
            al[0] = packbf(s[2*ks][0]   - bf_lo(ah[0]), s[2*ks][1]   - bf_hi(ah[0]));
            al[1] = packbf(s[2*ks][2]   - bf_lo(ah[1]), s[2*ks][3]   - bf_hi(ah[1]));
            al[2] = packbf(s[2*ks+1][0] - bf_lo(ah[2]), s[2*ks+1][1] - bf_hi(ah[2]));
            al[3] = packbf(s[2*ks+1][2] - bf_lo(ah[3]), s[2*ks+1][3] - bf_hi(ah[3]));

            uint32_t vb[8][2];
            #pragma unroll
            for (int g = 0; g < 4; g++) {
                uint32_t r[4];
                LDSM4T(r, bVh + (16*ks + vrowb)*AT_ROWB + g*32 + lhi*16);
                vb[2*g][0] = r[0]; vb[2*g][1] = r[1];
                vb[2*g+1][0] = r[2]; vb[2*g+1][1] = r[3];
            }
            #pragma unroll
            for (int nt = 0; nt < 8; nt++)
                MMA16816(o[nt], ah, vb[nt][0], vb[nt][1]);
            #pragma unroll
            for (int nt = 0; nt < 8; nt++)
                MMA16816(o[nt], al, vb[nt][0], vb[nt][1]);
            #pragma unroll
            for (int g = 0; g < 4; g++) {
                uint32_t r[4];
                LDSM4T(r, bVl + (16*ks + vrowb)*AT_ROWB + g*32 + lhi*16);
                vb[2*g][0] = r[0]; vb[2*g][1] = r[1];
                vb[2*g+1][0] = r[2]; vb[2*g+1][1] = r[3];
            }
            #pragma unroll
            for (int nt = 0; nt < 8; nt++)
                MMA16816(o[nt], ah, vb[nt][0], vb[nt][1]);
        }
        __syncthreads();
    }
    #undef AT_LOAD

    const float inv0 = 1.f / l0, inv1 = 1.f / l1;
    const int b = bh >> 4, h = bh & 15;
    const size_t base0 = (((size_t)b*TT + r0g) << 10) + (h << 6);
    const size_t base1 = (((size_t)b*TT + r1g) << 10) + (h << 6);
    #pragma unroll
    for (int nt = 0; nt < 8; nt++) {
        int d = nt*8 + (lane & 3)*2;
        float v0 = o[nt][0]*inv0, v1 = o[nt][1]*inv0;
        float v2 = o[nt][2]*inv1, v3 = o[nt][3]*inv1;
        uint32_t h01 = packbf(v0, v1);
        uint32_t h23 = packbf(v2, v3);
        *(uint32_t*)(g_Ah + base0 + d) = h01;
        *(uint32_t*)(g_Ah + base1 + d) = h23;
        *(uint32_t*)(g_Al + base0 + d) = packbf(v0 - bf_lo(h01), v1 - bf_hi(h01));
        *(uint32_t*)(g_Al + base1 + d) = packbf(v2 - bf_lo(h23), v3 - bf_hi(h23));
    }
}

// ---------------------------------------------------------------------------
// Split Wu fp32 -> (hi, lo) bf16.
// ---------------------------------------------------------------------------
__global__ __launch_bounds__(256) void split_W_kernel(const float* __restrict__ src)
{
    int i = blockIdx.x*256 + threadIdx.x;
    float4 v = ((const float4*)src)[i];
    float f[4] = {v.x, v.y, v.z, v.w};
    __nv_bfloat16 h[4], l[4];
    #pragma unroll
    for (int j = 0; j < 4; j++) {
        h[j] = __float2bfloat16(f[j]);
        l[j] = __float2bfloat16(f[j] - __bfloat162float(h[j]));
    }
    __nv_bfloat162* hp = (__nv_bfloat162*)g_Wh;
    __nv_bfloat162* lp = (__nv_bfloat162*)g_Wl;
    hp[i*2+0] = __nv_bfloat162(h[0], h[1]);
    hp[i*2+1] = __nv_bfloat162(h[2], h[3]);
    lp[i*2+0] = __nv_bfloat162(l[0], l[1]);
    lp[i*2+1] = __nv_bfloat162(l[2], l[3]);
}

// ---------------------------------------------------------------------------
// Kernel 3: out = A @ Wu^T + bu — fused 3-product split-precision GEMM.
// CTA 256(M) x 128(N), 512 threads (16 warps, 4m x 4n), warp tile 64x32.
// Per K-chunk (64): load Ah, Al, Wh, Wl tiles; issue Ah*Bh, Al*Bh, Ah*Bl.
// 16 loop iterations (vs 48), double-buffered.
// ---------------------------------------------------------------------------
#define SPAD 72
#define G_AH 0
#define G_AL 36864               // 256*144
#define G_BH 73728
#define G_BL 92160               // +128*144
#define GBUF 110592
#define GEMM_SMEM (2*GBUF)       // 221184

__global__ __launch_bounds__(512, 1) void out_gemm_mma(
    const float* __restrict__ bu,
    float* __restrict__ out)
{
    extern __shared__ __align__(16) char smc[];
    const uint32_t sb = smem_u32(smc);

    const int tid  = threadIdx.x;
    const int warp = tid >> 5;
    const int lane = tid & 31;
    const int m0 = blockIdx.y << 8;
    const int n0 = blockIdx.x << 7;

    const int wm = warp >> 2;          // 0..3 -> m offset wm*64
    const int wn = warp & 3;           // 0..3 -> n offset wn*32

    const int a_row = (lane & 7) + ((lane >> 3) & 1) * 8;
    const int a_kh  = (lane >> 4) * 8;
    const int b_row = (lane & 7) + ((lane >> 4) & 1) * 8;
    const int b_kh  = ((lane >> 3) & 1) * 8;

    float acc[4][4][4];
    #pragma unroll
    for (int i = 0; i < 4; i++)
        #pragma unroll
        for (int j = 0; j < 4; j++)
            #pragma unroll
            for (int q = 0; q < 4; q++) acc[i][j][q] = 0.f;

    // Load one K-chunk (64 cols) of all four tiles.
    #define LOAD_CHUNK(kc_, buf_) do {                                        \
        int k0_ = (kc_) << 6;                                                 \
        uint32_t base_ = sb + (buf_) * GBUF;                                  \
        _Pragma("unroll")                                                     \
        for (int i_ = 0; i_ < 4; i_++) {                                      \
            int o_ = tid + (i_ << 9);                                         \
            int row_ = o_ >> 3, seg_ = o_ & 7;                                \
            size_t s_ = (((size_t)(m0 + row_)) << 10) + k0_ + seg_*8;         \
            uint32_t d_ = row_*144 + seg_*16;                                 \
            CP16(base_ + G_AH + d_, g_Ah + s_);                               \
            CP16(base_ + G_AL + d_, g_Al + s_);                               \
        }                                                                     \
        _Pragma("unroll")                                                     \
        for (int i_ = 0; i_ < 2; i_++) {                                      \
            int o_ = tid + (i_ << 9);                                         \
            int row_ = o_ >> 3, seg_ = o_ & 7;                                \
            size_t s_ = (((size_t)(n0 + row_)) << 10) + k0_ + seg_*8;         \
            uint32_t d_ = row_*144 + seg_*16;                                 \
            CP16(base_ + G_BH + d_, g_Wh + s_);                               \
            CP16(base_ + G_BL + d_, g_Wl + s_);                               \
        }                                                                     \
        asm volatile("cp.async.commit_group;" ::: "memory");                  \
    } while (0)

    LOAD_CHUNK(0, 0);

    #pragma unroll 1
    for (int kc = 0; kc < 16; kc++) {
        const int buf = kc & 1;
        if (kc + 1 < 16) {
            LOAD_CHUNK(kc + 1, buf ^ 1);
            asm volatile("cp.async.wait_group 1;" ::: "memory");
        } else {
            asm volatile("cp.async.wait_group 0;" ::: "memory");
        }
        __syncthreads();

        const uint32_t base = sb + buf * GBUF;

        #pragma unroll
        for (int ks = 0; ks < 4; ks++) {
            const uint32_t aoff = (uint32_t)(((wm*64 + a_row) * SPAD + ks*16 + a_kh) * 2);
            const uint32_t boff = (uint32_t)(((wn*32 + b_row) * SPAD + ks*16 + b_kh) * 2);

            uint32_t ah[4][4];
            #pragma unroll
            for (int mi = 0; mi < 4; mi++)
                LDSM4(ah[mi], base + G_AH + aoff + (uint32_t)(mi*16*SPAD*2));

            uint32_t bh[2][4];
            #pragma unroll
            for (int bj = 0; bj < 2; bj++)
                LDSM4(bh[bj], base + G_BH + boff + (uint32_t)(bj*16*SPAD*2));

            // Ah * Bh
            #pragma unroll
            for (int mi = 0; mi < 4; mi++)
                #pragma unroll
                for (int nj = 0; nj < 4; nj++)
                    MMA16816(acc[mi][nj], ah[mi],
                             bh[nj >> 1][(nj & 1)*2], bh[nj >> 1][(nj & 1)*2 + 1]);

            // Al * Bh
            {
                uint32_t al[4][4];
                #pragma unroll
                for (int mi = 0; mi < 4; mi++)
                    LDSM4(al[mi], base + G_AL + aoff + (uint32_t)(mi*16*SPAD*2));
                #pragma unroll
                for (int mi = 0; mi < 4; mi++)
                    #pragma unroll
                    for (int nj = 0; nj < 4; nj++)
                        MMA16816(acc[mi][nj], al[mi],
                                 bh[nj >> 1][(nj & 1)*2], bh[nj >> 1][(nj & 1)*2 + 1]);
            }

            // Ah * Bl
            {
                uint32_t bl[2][4];
                #pragma unroll
                for (int bj = 0; bj < 2; bj++)
                    LDSM4(bl[bj], base + G_BL + boff + (uint32_t)(bj*16*SPAD*2));
                #pragma unroll
                for (int mi = 0; mi < 4; mi++)
                    #pragma unroll
                    for (int nj = 0; nj < 4; nj++)
                        MMA16816(acc[mi][nj], ah[mi],
                                 bl[nj >> 1][(nj & 1)*2], bl[nj >> 1][(nj & 1)*2 + 1]);
            }
        }
        __syncthreads();
    }

    const int r0 = lane >> 2;
    const int cp = (lane & 3) * 2;
    #pragma unroll
    for (int mi = 0; mi < 4; mi++) {
        #pragma unroll
        for (int nj = 0; nj < 4; nj++) {
            int gm = m0 + wm*64 + mi*16 + r0;
            int gn = n0 + wn*32 + nj*8 + cp;
            float b0 = bu[gn], b1 = bu[gn + 1];
            float2 v0 = make_float2(acc[mi][nj][0] + b0, acc[mi][nj][1] + b1);
            float2 v1 = make_float2(acc[mi][nj][2] + b0, acc[mi][nj][3] + b1);
            *(float2*)(out + ((size_t)gm << 10) + gn)       = v0;
            *(float2*)(out + ((size_t)(gm + 8) << 10) + gn) = v1;
        }
    }
    #undef LOAD_CHUNK
}

// ---------------------------------------------------------------------------
extern "C" void kernel_launch(void* const* d_in, const int* in_sizes, int n_in,
                              void* d_out, int out_size)
{
    (void)in_sizes; (void)n_in; (void)out_size;
    const float* x       = (const float*)d_in[0];
    const int*   lengths = (const int*)  d_in[1];
    const float* Wk      = (const float*)d_in[2];
    const float* Wq      = (const float*)d_in[3];
    const float* Wv      = (const float*)d_in[4];
    const float* Wu      = (const float*)d_in[5];
    const float* bu      = (const float*)d_in[6];
    float* out = (float*)d_out;

    cudaFuncSetAttribute(qkv_mma, cudaFuncAttributeMaxDynamicSharedMemorySize,
                         QK_SMEM);
    cudaFuncSetAttribute(attn_mma, cudaFuncAttributeMaxDynamicSharedMemorySize,
                         AT_SMEM);
    cudaFuncSetAttribute(out_gemm_mma, cudaFuncAttributeMaxDynamicSharedMemorySize,
                         GEMM_SMEM);

    split_W_kernel<<<(EE*EE/4)/256, 256>>>(Wu);
    qkv_mma<<<(BB*TT*HH)/128, 256, QK_SMEM>>>(x, Wq, Wk, Wv);
    attn_mma<<<dim3(TT/128, BB*HH), 256, AT_SMEM>>>(lengths);
    out_gemm_mma<<<dim3(EE/128, (BB*TT)/256), 512, GEMM_SMEM>>>(bu, out);
}